// round 8
// baseline (speedup 1.0000x reference)
#include <cuda_runtime.h>

#define NWIN  64
#define NHEAD 12
#define LTOK  343
#define HEADD 32
#define DIMM  384
#define TBLN  2197
#define L2TOK (LTOK*LTOK)
#define QSCALE 0.17677669529663687f   // 32^-0.5
#define MROWS (NWIN*LTOK)             // 21952

// permuted k index: pairs (k, k+4) adjacent -> LDS.64 fragment loads
#define PK(k) ((((k) & 3) << 2) | (((k) >> 2) & 1) | ((((k) >> 3) & 1) << 1))

// -------- scratch (static device globals; no runtime allocation) --------
__device__ __align__(16) float g_q[(size_t)NWIN*NHEAD*LTOK*HEADD];
__device__ __align__(16) float g_k[(size_t)NWIN*NHEAD*LTOK*HEADD];
__device__ __align__(16) float g_v[(size_t)NWIN*NHEAD*LTOK*HEADD];
__device__ __align__(16) float g_ao[(size_t)MROWS*DIMM];
__device__ __align__(16) float g_biasT[(size_t)NHEAD*L2TOK];        // [h][j][i]
__device__ __align__(16) unsigned char g_maskT[(size_t)NWIN*L2TOK]; // [n][j][i]
__device__ int g_mask_mode;   // 0 = 1-byte elements, 1 = 4-byte elements

// ======================================================================
__global__ void detect_mask_kernel(const unsigned int* __restrict__ m)
{
    __shared__ int s_not01, s_notf;
    if (threadIdx.x == 0) { s_not01 = 0; s_notf = 0; }
    __syncthreads();
    int bad01 = 0, badf = 0;
    for (int i = threadIdx.x; i < 4096; i += 256) {
        unsigned int w = m[i];
        if (w > 1u) bad01 = 1;
        if (w != 0u && w != 0x3F800000u) badf = 1;
    }
    if (bad01) atomicOr(&s_not01, 1);
    if (badf)  atomicOr(&s_notf, 1);
    __syncthreads();
    if (threadIdx.x == 0)
        g_mask_mode = (!s_not01 || !s_notf) ? 1 : 0;
}

// ======================================================================
// biasT[h][j][i] = table[rel_idx[i][j]][h], 32x32 smem-tile transpose
// ======================================================================
__global__ void biast_prep_kernel(const float* __restrict__ table,
                                  const int* __restrict__ rel_idx)
{
    __shared__ int tile[32][33];
    const int tx = threadIdx.x, ty = threadIdx.y;
    const int i0 = blockIdx.x * 32, j0 = blockIdx.y * 32;

    int i = i0 + ty, j = j0 + tx;
    if (i < LTOK && j < LTOK)
        tile[ty][tx] = rel_idx[(size_t)i * LTOK + j];
    __syncthreads();

    int oj = j0 + ty, oi = i0 + tx;
    if (oj < LTOK && oi < LTOK) {
        int idx = tile[tx][ty];
        const float* trow = table + (size_t)idx * NHEAD;
        size_t dst = (size_t)oj * LTOK + oi;
        #pragma unroll
        for (int h = 0; h < NHEAD; h++)
            g_biasT[(size_t)h * L2TOK + dst] = trow[h];
    }
}

// ======================================================================
// maskT[n][j][i] = mask[n][i][j] != 0, 32x32 smem-tile transpose
// ======================================================================
__global__ void maskt_prep_kernel(const void* __restrict__ mask)
{
    __shared__ unsigned char tile[32][33];
    const int tx = threadIdx.x, ty = threadIdx.y;
    const int i0 = blockIdx.x * 32, j0 = blockIdx.y * 32;
    const int n  = blockIdx.z;
    const int mmode = g_mask_mode;

    int i = i0 + ty, j = j0 + tx;
    if (i < LTOK && j < LTOK) {
        size_t src = (size_t)n * L2TOK + (size_t)i * LTOK + j;
        bool mm = mmode ? (((const unsigned int*)mask)[src] != 0u)
                        : (((const unsigned char*)mask)[src] != 0);
        tile[ty][tx] = mm ? 1 : 0;
    }
    __syncthreads();

    int oj = j0 + ty, oi = i0 + tx;
    if (oj < LTOK && oi < LTOK)
        g_maskT[(size_t)n * L2TOK + (size_t)oj * LTOK + oi] = tile[tx][ty];
}

// ======================================================================
// tf32 helpers
// ======================================================================
__device__ __forceinline__ unsigned f2tf32(float f)
{
    unsigned r;
    asm("cvt.rna.tf32.f32 %0, %1;" : "=r"(r) : "f"(f));
    return r;
}

__device__ __forceinline__ void mma_tf32(float c[4], const unsigned a[4],
                                         const unsigned b[2])
{
    asm volatile(
        "mma.sync.aligned.m16n8k8.row.col.f32.tf32.tf32.f32 "
        "{%0,%1,%2,%3}, {%4,%5,%6,%7}, {%8,%9}, {%0,%1,%2,%3};"
        : "+f"(c[0]), "+f"(c[1]), "+f"(c[2]), "+f"(c[3])
        : "r"(a[0]), "r"(a[1]), "r"(a[2]), "r"(a[3]),
          "r"(b[0]), "r"(b[1]));
}

// ======================================================================
// tf32 tensor-core GEMM, permuted-k smem + LDS.64 fragment loads.
// BM=128, BN=64, BK=16; 256 threads = 8 warps (4x2), 32x32 warp tile.
// mode 0: C = g_ao @ B + bias     mode 1: scatter x@qkv_w into g_q/k/v
// ======================================================================
__global__ __launch_bounds__(256)
void mm_tf32_kernel(const float* __restrict__ Ain, const float* __restrict__ B,
                    int M, int N, int K, int mode,
                    float* __restrict__ C, const float* __restrict__ bias)
{
    __shared__ unsigned As[128][20];   // [m][PK(k)], padded
    __shared__ unsigned BsT[64][22];   // [n][PK(k)], padded

    const float* A = (mode == 0) ? g_ao : Ain;
    const int tid  = threadIdx.x;
    const int warp = tid >> 5, lane = tid & 31;
    const int wm   = warp & 3;
    const int wn   = warp >> 2;
    const int gid  = lane >> 2, tig = lane & 3;
    const int bm   = blockIdx.x * 128, bn = blockIdx.y * 64;

    float c[2][4][4];
    #pragma unroll
    for (int mt = 0; mt < 2; mt++)
        #pragma unroll
        for (int nt = 0; nt < 4; nt++)
            #pragma unroll
            for (int e = 0; e < 4; e++) c[mt][nt][e] = 0.f;

    for (int k0 = 0; k0 < K; k0 += 16) {
        // stage A tile (128 x 16), permuted k
        #pragma unroll
        for (int i = 0; i < 2; i++) {
            int t  = tid + i * 256;
            int m  = t >> 2;
            int c4 = (t & 3) << 2;
            int gr = bm + m;
            float4 v = make_float4(0.f, 0.f, 0.f, 0.f);
            if (gr < M) v = *(const float4*)(A + (size_t)gr * K + k0 + c4);
            As[m][PK(c4 + 0)] = f2tf32(v.x);
            As[m][PK(c4 + 1)] = f2tf32(v.y);
            As[m][PK(c4 + 2)] = f2tf32(v.z);
            As[m][PK(c4 + 3)] = f2tf32(v.w);
        }
        // stage B tile (16 x 64) transposed, permuted k
        {
            int kr = tid >> 4;
            int c4 = (tid & 15) << 2;
            int pk = PK(kr);
            float4 v = *(const float4*)(B + (size_t)(k0 + kr) * N + bn + c4);
            BsT[c4 + 0][pk] = f2tf32(v.x);
            BsT[c4 + 1][pk] = f2tf32(v.y);
            BsT[c4 + 2][pk] = f2tf32(v.z);
            BsT[c4 + 3][pk] = f2tf32(v.w);
        }
        __syncthreads();

        #pragma unroll
        for (int ks = 0; ks < 16; ks += 8) {
            const int off = 4 * tig + (ks >> 2);
            unsigned af[2][4], bf[4][2];
            #pragma unroll
            for (int mt = 0; mt < 2; mt++) {
                int mr = wm * 32 + mt * 16 + gid;
                uint2 lo = *(const uint2*)&As[mr][off];
                uint2 hi = *(const uint2*)&As[mr + 8][off];
                af[mt][0] = lo.x; af[mt][1] = hi.x;
                af[mt][2] = lo.y; af[mt][3] = hi.y;
            }
            #pragma unroll
            for (int nt = 0; nt < 4; nt++) {
                int nc = wn * 32 + nt * 8 + gid;
                uint2 b2 = *(const uint2*)&BsT[nc][off];
                bf[nt][0] = b2.x; bf[nt][1] = b2.y;
            }
            #pragma unroll
            for (int mt = 0; mt < 2; mt++)
                #pragma unroll
                for (int nt = 0; nt < 4; nt++)
                    mma_tf32(c[mt][nt], af[mt], bf[nt]);
        }
        __syncthreads();
    }

    // ---- epilogue ----
    #pragma unroll
    for (int mt = 0; mt < 2; mt++) {
        int r0 = bm + wm * 32 + mt * 16 + gid;
        int r1 = r0 + 8;
        if (mode == 0) {
            #pragma unroll
            for (int nt = 0; nt < 4; nt++) {
                int col = bn + wn * 32 + nt * 8 + tig * 2;
                float bx = bias[col], by = bias[col + 1];
                if (r0 < M) {
                    float2 o = make_float2(c[mt][nt][0] + bx, c[mt][nt][1] + by);
                    *(float2*)(C + (size_t)r0 * N + col) = o;
                }
                if (r1 < M) {
                    float2 o = make_float2(c[mt][nt][2] + bx, c[mt][nt][3] + by);
                    *(float2*)(C + (size_t)r1 * N + col) = o;
                }
            }
        } else {
            int n0 = r0 / LTOK, l0 = r0 - n0 * LTOK;
            int n1 = r1 / LTOK, l1 = r1 - n1 * LTOK;
            #pragma unroll
            for (int nt = 0; nt < 4; nt++) {
                int colb = bn + wn * 32 + nt * 8 + tig * 2;
                #pragma unroll
                for (int e = 0; e < 4; e++) {
                    int row = (e < 2) ? r0 : r1;
                    if (row >= M) continue;
                    int nn  = (e < 2) ? n0 : n1;
                    int ll  = (e < 2) ? l0 : l1;
                    int col = colb + (e & 1);
                    int s   = col / DIMM;
                    int rem = col - s * DIMM;
                    int hh  = rem >> 5;
                    int cc  = rem & 31;
                    float* dst = (s == 0) ? g_q : ((s == 1) ? g_k : g_v);
                    dst[(((size_t)(nn * NHEAD + hh)) * LTOK + ll) * HEADD + cc]
                        = c[mt][nt][e];
                }
            }
        }
    }
}

// ======================================================================
// Fused window attention: block(512) per (window, head).
// Score: lane-owns-q, K broadcast. AV: 512 threads, 4-way kj split.
// ======================================================================
__global__ __launch_bounds__(512)
void attn_kernel()
{
    extern __shared__ float sm[];
    float* Ks  = sm;                      // [343][36]
    float* Vs  = Ks + LTOK * 36;          // [343][36]
    float* SsT = Vs + LTOK * 36;          // [343][64]
    float* Pp  = SsT + LTOK * 64;         // [4][64][36] AV partials
    float* Red = Pp + 4 * 64 * 36;        // [8][64]
    float* Mf  = Red + 512;               // [64]
    float* Sf  = Mf + 64;                 // [64]

    const int tid  = threadIdx.x;
    const int warp = tid >> 5;
    const int lane = tid & 31;
    const int bh   = blockIdx.x;
    const int n    = bh / NHEAD;
    const int h    = bh - n * NHEAD;

    const int g  = warp >> 3;
    const int r  = warp & 7;
    const int k0r = r * 43;
    const int k1r = min(k0r + 43, LTOK);
    const int qt  = g * 32 + lane;

    const float* bias_h = g_biasT + (size_t)h * L2TOK;
    const unsigned char* mT = g_maskT + (size_t)n * L2TOK;

    const float* kg = g_k + (size_t)bh * LTOK * HEADD;
    const float* vg = g_v + (size_t)bh * LTOK * HEADD;
    for (int i = tid; i < LTOK * 8; i += 512) {
        int row = i >> 3, c4 = (i & 7) << 2;
        *(float4*)&Ks[row * 36 + c4] = *(const float4*)(kg + (size_t)i * 4);
        *(float4*)&Vs[row * 36 + c4] = *(const float4*)(vg + (size_t)i * 4);
    }
    __syncthreads();

    const float* qg = g_q + (size_t)bh * LTOK * HEADD;

    for (int q0 = 0; q0 < LTOK; q0 += 64) {
        const int qn = min(64, LTOK - q0);
        const int qglob = q0 + qt;

        float4 Q[8];
        {
            const float* qrow = qg + (size_t)min(qglob, LTOK - 1) * HEADD;
            #pragma unroll
            for (int c = 0; c < 8; c++) Q[c] = *(const float4*)(qrow + c * 4);
        }

        // ---- scores + online max ----
        float mloc = -1e30f;
        for (int kj = k0r; kj < k1r; kj++) {
            const float* krow = Ks + kj * 36;
            float p0 = 0.f, p1 = 0.f, p2 = 0.f, p3 = 0.f;
            #pragma unroll
            for (int c = 0; c < 2; c++) {
                float4 k0 = *(const float4*)(krow + (c * 4 + 0) * 4);
                float4 k1 = *(const float4*)(krow + (c * 4 + 1) * 4);
                float4 k2 = *(const float4*)(krow + (c * 4 + 2) * 4);
                float4 k3 = *(const float4*)(krow + (c * 4 + 3) * 4);
                float4 q0v = Q[c * 4 + 0], q1v = Q[c * 4 + 1];
                float4 q2v = Q[c * 4 + 2], q3v = Q[c * 4 + 3];
                p0 = fmaf(q0v.x, k0.x, fmaf(q0v.y, k0.y,
                     fmaf(q0v.z, k0.z, fmaf(q0v.w, k0.w, p0))));
                p1 = fmaf(q1v.x, k1.x, fmaf(q1v.y, k1.y,
                     fmaf(q1v.z, k1.z, fmaf(q1v.w, k1.w, p1))));
                p2 = fmaf(q2v.x, k2.x, fmaf(q2v.y, k2.y,
                     fmaf(q2v.z, k2.z, fmaf(q2v.w, k2.w, p2))));
                p3 = fmaf(q3v.x, k3.x, fmaf(q3v.y, k3.y,
                     fmaf(q3v.z, k3.z, fmaf(q3v.w, k3.w, p3))));
            }
            float dot = (p0 + p1) + (p2 + p3);
            size_t off = (size_t)kj * LTOK + qglob;
            float s = mT[off] ? -1e30f : fmaf(dot, QSCALE, bias_h[off]);
            mloc = fmaxf(mloc, s);
            SsT[kj * 64 + qt] = s;
        }
        Red[r * 64 + qt] = mloc;
        __syncthreads();

        if (tid < 64) {
            float m = Red[tid];
            #pragma unroll
            for (int rr = 1; rr < 8; rr++) m = fmaxf(m, Red[rr * 64 + tid]);
            Mf[tid] = m;
        }
        __syncthreads();

        // ---- exp + partial sum ----
        {
            float mq = Mf[qt];
            float ssum = 0.f;
            for (int kj = k0r; kj < k1r; kj++) {
                float p = __expf(SsT[kj * 64 + qt] - mq);
                SsT[kj * 64 + qt] = p;
                ssum += p;
            }
            Red[r * 64 + qt] = ssum;
        }
        __syncthreads();

        if (tid < 64) {
            float s = Red[tid];
            #pragma unroll
            for (int rr = 1; rr < 8; rr++) s += Red[rr * 64 + tid];
            Sf[tid] = 1.f / s;
        }
        __syncthreads();

        // ---- AV: all 512 threads, kj split 4 ways ----
        {
            const int gg  = tid >> 7;         // 0..3 kj group
            const int t   = tid & 127;
            const int qgp = t >> 3;           // q-group of 4
            const int cg  = t & 7;            // channel group of 4
            const int kja = gg * 86;
            const int kjb = min(kja + 86, LTOK);
            float4 a0 = make_float4(0.f, 0.f, 0.f, 0.f);
            float4 a1 = make_float4(0.f, 0.f, 0.f, 0.f);
            float4 a2 = make_float4(0.f, 0.f, 0.f, 0.f);
            float4 a3 = make_float4(0.f, 0.f, 0.f, 0.f);
            const float* sp = SsT + qgp * 4;
            const float* vp = Vs + cg * 4;
            #pragma unroll 4
            for (int j = kja; j < kjb; j++) {
                float4 pv = *(const float4*)(sp + j * 64);
                float4 vv = *(const float4*)(vp + j * 36);
                a0.x = fmaf(pv.x, vv.x, a0.x);
                a0.y = fmaf(pv.x, vv.y, a0.y);
                a0.z = fmaf(pv.x, vv.z, a0.z);
                a0.w = fmaf(pv.x, vv.w, a0.w);
                a1.x = fmaf(pv.y, vv.x, a1.x);
                a1.y = fmaf(pv.y, vv.y, a1.y);
                a1.z = fmaf(pv.y, vv.z, a1.z);
                a1.w = fmaf(pv.y, vv.w, a1.w);
                a2.x = fmaf(pv.z, vv.x, a2.x);
                a2.y = fmaf(pv.z, vv.y, a2.y);
                a2.z = fmaf(pv.z, vv.z, a2.z);
                a2.w = fmaf(pv.z, vv.w, a2.w);
                a3.x = fmaf(pv.w, vv.x, a3.x);
                a3.y = fmaf(pv.w, vv.y, a3.y);
                a3.z = fmaf(pv.w, vv.z, a3.z);
                a3.w = fmaf(pv.w, vv.w, a3.w);
            }
            float* pbase = Pp + ((size_t)gg * 64 + qgp * 4) * 36 + cg * 4;
            *(float4*)(pbase + 0 * 36) = a0;
            *(float4*)(pbase + 1 * 36) = a1;
            *(float4*)(pbase + 2 * 36) = a2;
            *(float4*)(pbase + 3 * 36) = a3;
        }
        __syncthreads();

        // ---- reduce partials + write out (512 tasks exactly) ----
        {
            const int q  = tid >> 3;
            const int cg = tid & 7;
            const float* pb = Pp + (size_t)q * 36 + cg * 4;
            float4 s0 = *(const float4*)(pb + 0 * 64 * 36);
            float4 s1 = *(const float4*)(pb + 1 * 64 * 36);
            float4 s2 = *(const float4*)(pb + 2 * 64 * 36);
            float4 s3 = *(const float4*)(pb + 3 * 64 * 36);
            if (q < qn) {
                float inv = Sf[q];
                float4 o;
                o.x = (s0.x + s1.x + s2.x + s3.x) * inv;
                o.y = (s0.y + s1.y + s2.y + s3.y) * inv;
                o.z = (s0.z + s1.z + s2.z + s3.z) * inv;
                o.w = (s0.w + s1.w + s2.w + s3.w) * inv;
                float* og = g_ao + ((size_t)(n * LTOK + q0 + q)) * DIMM
                            + h * HEADD + cg * 4;
                *(float4*)og = o;
            }
        }
        __syncthreads();
    }
}

// ======================================================================
extern "C" void kernel_launch(void* const* d_in, const int* in_sizes, int n_in,
                              void* d_out, int out_size)
{
    const float *x = nullptr, *qkvw = nullptr, *tbl = nullptr;
    const float *pw = nullptr, *pb = nullptr;
    const void* mask = nullptr;
    const int* ridx = nullptr;
    for (int i = 0; i < n_in; i++) {
        switch (in_sizes[i]) {
            case 8429568:  x    = (const float*)d_in[i]; break;
            case 442368:   qkvw = (const float*)d_in[i]; break;
            case 26364:    tbl  = (const float*)d_in[i]; break;
            case 147456:   pw   = (const float*)d_in[i]; break;
            case 384:      pb   = (const float*)d_in[i]; break;
            case 7530496:  mask = d_in[i]; break;
            case 117649:   ridx = (const int*)d_in[i]; break;
        }
    }
    if (n_in >= 7) {
        if (!x)    x    = (const float*)d_in[0];
        if (!qkvw) qkvw = (const float*)d_in[1];
        if (!tbl)  tbl  = (const float*)d_in[2];
        if (!pw)   pw   = (const float*)d_in[3];
        if (!pb)   pb   = (const float*)d_in[4];
        if (!mask) mask = d_in[5];
        if (!ridx) ridx = (const int*)d_in[6];
    }

    // 0) prep: mask dtype, tiled-transposed bias / mask
    detect_mask_kernel<<<1, 256>>>((const unsigned int*)mask);
    dim3 tb(32, 32);
    dim3 tg(11, 11);
    biast_prep_kernel<<<tg, tb>>>(tbl, ridx);
    maskt_prep_kernel<<<dim3(11, 11, NWIN), tb>>>(mask);

    // 1) QKV projection (tf32 tensor cores) + scatter
    mm_tf32_kernel<<<dim3(172, 18), 256>>>(x, qkvw, MROWS, 3 * DIMM, DIMM, 1,
                                           nullptr, nullptr);

    // 2) fused attention
    size_t smem = (size_t)(LTOK * 36 * 2 + LTOK * 64 + 4 * 64 * 36 + 512
                           + 64 + 64) * sizeof(float);
    cudaFuncSetAttribute(attn_kernel,
                         cudaFuncAttributeMaxDynamicSharedMemorySize, (int)smem);
    attn_kernel<<<NWIN * NHEAD, 512, smem>>>();

    // 3) output projection (tf32 tensor cores) + bias
    mm_tf32_kernel<<<dim3(172, 6), 256>>>(nullptr, pw, MROWS, DIMM, DIMM, 0,
                                          (float*)d_out, pb);
}

// round 9
// speedup vs baseline: 1.0417x; 1.0417x over previous
#include <cuda_runtime.h>

#define NWIN  64
#define NHEAD 12
#define LTOK  343
#define HEADD 32
#define DIMM  384
#define TBLN  2197
#define L2TOK (LTOK*LTOK)
#define QSCALE 0.17677669529663687f   // 32^-0.5
#define MROWS (NWIN*LTOK)             // 21952

// -------- scratch (static device globals; no runtime allocation) --------
__device__ __align__(16) float g_q[(size_t)NWIN*NHEAD*LTOK*HEADD];
__device__ __align__(16) float g_k[(size_t)NWIN*NHEAD*LTOK*HEADD];
__device__ __align__(16) float g_v[(size_t)NWIN*NHEAD*LTOK*HEADD];
__device__ __align__(16) float g_ao[(size_t)MROWS*DIMM];
__device__ __align__(16) float g_biasT[(size_t)NHEAD*L2TOK];        // [h][j][i]
__device__ __align__(16) unsigned char g_maskT[(size_t)NWIN*L2TOK]; // [n][j][i]
__device__ int g_mask_mode;   // 0 = 1-byte elements, 1 = 4-byte elements

// ======================================================================
__global__ void detect_mask_kernel(const unsigned int* __restrict__ m)
{
    __shared__ int s_not01, s_notf;
    if (threadIdx.x == 0) { s_not01 = 0; s_notf = 0; }
    __syncthreads();
    int bad01 = 0, badf = 0;
    for (int i = threadIdx.x; i < 4096; i += 256) {
        unsigned int w = m[i];
        if (w > 1u) bad01 = 1;
        if (w != 0u && w != 0x3F800000u) badf = 1;
    }
    if (bad01) atomicOr(&s_not01, 1);
    if (badf)  atomicOr(&s_notf, 1);
    __syncthreads();
    if (threadIdx.x == 0)
        g_mask_mode = (!s_not01 || !s_notf) ? 1 : 0;
}

// ======================================================================
// Merged prep (one launch so attn becomes ncu's captured launch #3):
//  z in [0,64): maskT[n][j][i] = mask[n][i][j] != 0   (32x32 tile transpose)
//  z == 64:     biasT[h][j][i] = table[rel_idx[i][j]][h]
// ======================================================================
__global__ void prep_kernel(const void* __restrict__ mask,
                            const float* __restrict__ table,
                            const int* __restrict__ rel_idx)
{
    const int tx = threadIdx.x, ty = threadIdx.y;
    const int i0 = blockIdx.x * 32, j0 = blockIdx.y * 32;
    const int z  = blockIdx.z;

    if (z < NWIN) {
        __shared__ unsigned char mt[32][33];
        const int mmode = g_mask_mode;
        int i = i0 + ty, j = j0 + tx;
        if (i < LTOK && j < LTOK) {
            size_t src = (size_t)z * L2TOK + (size_t)i * LTOK + j;
            bool mm = mmode ? (((const unsigned int*)mask)[src] != 0u)
                            : (((const unsigned char*)mask)[src] != 0);
            mt[ty][tx] = mm ? 1 : 0;
        }
        __syncthreads();
        int oj = j0 + ty, oi = i0 + tx;
        if (oj < LTOK && oi < LTOK)
            g_maskT[(size_t)z * L2TOK + (size_t)oj * LTOK + oi] = mt[tx][ty];
    } else {
        __shared__ int it[32][33];
        int i = i0 + ty, j = j0 + tx;
        if (i < LTOK && j < LTOK)
            it[ty][tx] = rel_idx[(size_t)i * LTOK + j];
        __syncthreads();
        int oj = j0 + ty, oi = i0 + tx;
        if (oj < LTOK && oi < LTOK) {
            int idx = it[tx][ty];
            const float* trow = table + (size_t)idx * NHEAD;
            size_t dst = (size_t)oj * LTOK + oi;
            #pragma unroll
            for (int h = 0; h < NHEAD; h++)
                g_biasT[(size_t)h * L2TOK + dst] = trow[h];
        }
    }
}

// ======================================================================
// tf32 helpers
// ======================================================================
__device__ __forceinline__ unsigned f2tf32(float f)
{
    unsigned r;
    asm("cvt.rna.tf32.f32 %0, %1;" : "=r"(r) : "f"(f));
    return r;
}

__device__ __forceinline__ void mma_tf32(float c[4], const unsigned a[4],
                                         const unsigned b[2])
{
    asm volatile(
        "mma.sync.aligned.m16n8k8.row.col.f32.tf32.tf32.f32 "
        "{%0,%1,%2,%3}, {%4,%5,%6,%7}, {%8,%9}, {%0,%1,%2,%3};"
        : "+f"(c[0]), "+f"(c[1]), "+f"(c[2]), "+f"(c[3])
        : "r"(a[0]), "r"(a[1]), "r"(a[2]), "r"(a[3]),
          "r"(b[0]), "r"(b[1]));
}

// ======================================================================
// tf32 tensor-core GEMM (round-7 version, measured 237us for qkv).
// BM=128, BN=64, BK=16; 256 threads = 8 warps (4x2), 32x32 warp tile.
// mode 0: C = g_ao @ B + bias     mode 1: scatter x@qkv_w into g_q/k/v
// ======================================================================
__global__ __launch_bounds__(256)
void mm_tf32_kernel(const float* __restrict__ Ain, const float* __restrict__ B,
                    int M, int N, int K, int mode,
                    float* __restrict__ C, const float* __restrict__ bias)
{
    __shared__ unsigned As[128][18];   // [m][k], padded
    __shared__ unsigned Bs[16][72];    // [k][n], padded

    const float* A = (mode == 0) ? g_ao : Ain;
    const int tid  = threadIdx.x;
    const int warp = tid >> 5, lane = tid & 31;
    const int wm   = warp & 3;
    const int wn   = warp >> 2;
    const int gid  = lane >> 2, tig = lane & 3;
    const int bm   = blockIdx.x * 128, bn = blockIdx.y * 64;

    float c[2][4][4];
    #pragma unroll
    for (int mt = 0; mt < 2; mt++)
        #pragma unroll
        for (int nt = 0; nt < 4; nt++)
            #pragma unroll
            for (int e = 0; e < 4; e++) c[mt][nt][e] = 0.f;

    for (int k0 = 0; k0 < K; k0 += 16) {
        #pragma unroll
        for (int i = 0; i < 2; i++) {
            int t  = tid + i * 256;
            int m  = t >> 2;
            int c4 = (t & 3) << 2;
            int gr = bm + m;
            float4 v = make_float4(0.f, 0.f, 0.f, 0.f);
            if (gr < M) v = *(const float4*)(A + (size_t)gr * K + k0 + c4);
            As[m][c4 + 0] = f2tf32(v.x);
            As[m][c4 + 1] = f2tf32(v.y);
            As[m][c4 + 2] = f2tf32(v.z);
            As[m][c4 + 3] = f2tf32(v.w);
        }
        {
            int kr = tid >> 4;
            int c4 = (tid & 15) << 2;
            float4 v = *(const float4*)(B + (size_t)(k0 + kr) * N + bn + c4);
            Bs[kr][c4 + 0] = f2tf32(v.x);
            Bs[kr][c4 + 1] = f2tf32(v.y);
            Bs[kr][c4 + 2] = f2tf32(v.z);
            Bs[kr][c4 + 3] = f2tf32(v.w);
        }
        __syncthreads();

        #pragma unroll
        for (int ks = 0; ks < 16; ks += 8) {
            unsigned af[2][4], bf[4][2];
            #pragma unroll
            for (int mt = 0; mt < 2; mt++) {
                int mr = wm * 32 + mt * 16 + gid;
                af[mt][0] = As[mr][ks + tig];
                af[mt][1] = As[mr + 8][ks + tig];
                af[mt][2] = As[mr][ks + tig + 4];
                af[mt][3] = As[mr + 8][ks + tig + 4];
            }
            #pragma unroll
            for (int nt = 0; nt < 4; nt++) {
                int nc = wn * 32 + nt * 8 + gid;
                bf[nt][0] = Bs[ks + tig][nc];
                bf[nt][1] = Bs[ks + tig + 4][nc];
            }
            #pragma unroll
            for (int mt = 0; mt < 2; mt++)
                #pragma unroll
                for (int nt = 0; nt < 4; nt++)
                    mma_tf32(c[mt][nt], af[mt], bf[nt]);
        }
        __syncthreads();
    }

    #pragma unroll
    for (int mt = 0; mt < 2; mt++) {
        int r0 = bm + wm * 32 + mt * 16 + gid;
        int r1 = r0 + 8;
        if (mode == 0) {
            #pragma unroll
            for (int nt = 0; nt < 4; nt++) {
                int col = bn + wn * 32 + nt * 8 + tig * 2;
                float bx = bias[col], by = bias[col + 1];
                if (r0 < M) {
                    float2 o = make_float2(c[mt][nt][0] + bx, c[mt][nt][1] + by);
                    *(float2*)(C + (size_t)r0 * N + col) = o;
                }
                if (r1 < M) {
                    float2 o = make_float2(c[mt][nt][2] + bx, c[mt][nt][3] + by);
                    *(float2*)(C + (size_t)r1 * N + col) = o;
                }
            }
        } else {
            int n0 = r0 / LTOK, l0 = r0 - n0 * LTOK;
            int n1 = r1 / LTOK, l1 = r1 - n1 * LTOK;
            #pragma unroll
            for (int nt = 0; nt < 4; nt++) {
                int colb = bn + wn * 32 + nt * 8 + tig * 2;
                #pragma unroll
                for (int e = 0; e < 4; e++) {
                    int row = (e < 2) ? r0 : r1;
                    if (row >= M) continue;
                    int nn  = (e < 2) ? n0 : n1;
                    int ll  = (e < 2) ? l0 : l1;
                    int col = colb + (e & 1);
                    int s   = col / DIMM;
                    int rem = col - s * DIMM;
                    int hh  = rem >> 5;
                    int cc  = rem & 31;
                    float* dst = (s == 0) ? g_q : ((s == 1) ? g_k : g_v);
                    dst[(((size_t)(nn * NHEAD + hh)) * LTOK + ll) * HEADD + cc]
                        = c[mt][nt][e];
                }
            }
        }
    }
}

// ======================================================================
// Fused window attention (round-6/7 version): block(512) per (window, head).
// Score: lane-owns-q, K broadcast, online max. AV: 128 threads, 4q x 4c.
// ======================================================================
__global__ __launch_bounds__(512)
void attn_kernel()
{
    extern __shared__ float sm[];
    float* Ks  = sm;                      // [343][36]
    float* Vs  = Ks + LTOK * 36;          // [343][36]
    float* SsT = Vs + LTOK * 36;          // [343][64]
    float* Red = SsT + LTOK * 64;         // [8][64]
    float* Mf  = Red + 8 * 64;            // [64]
    float* Sf  = Mf + 64;                 // [64]

    const int tid  = threadIdx.x;
    const int warp = tid >> 5;
    const int lane = tid & 31;
    const int bh   = blockIdx.x;
    const int n    = bh / NHEAD;
    const int h    = bh - n * NHEAD;

    const int g  = warp >> 3;
    const int r  = warp & 7;
    const int k0r = r * 43;
    const int k1r = min(k0r + 43, LTOK);
    const int qt  = g * 32 + lane;

    const float* bias_h = g_biasT + (size_t)h * L2TOK;
    const unsigned char* mT = g_maskT + (size_t)n * L2TOK;

    const float* kg = g_k + (size_t)bh * LTOK * HEADD;
    const float* vg = g_v + (size_t)bh * LTOK * HEADD;
    for (int i = tid; i < LTOK * 8; i += 512) {
        int row = i >> 3, c4 = (i & 7) << 2;
        *(float4*)&Ks[row * 36 + c4] = *(const float4*)(kg + (size_t)i * 4);
        *(float4*)&Vs[row * 36 + c4] = *(const float4*)(vg + (size_t)i * 4);
    }
    __syncthreads();

    const float* qg = g_q + (size_t)bh * LTOK * HEADD;

    for (int q0 = 0; q0 < LTOK; q0 += 64) {
        const int qn = min(64, LTOK - q0);
        const int qglob = q0 + qt;

        float4 Q[8];
        {
            const float* qrow = qg + (size_t)min(qglob, LTOK - 1) * HEADD;
            #pragma unroll
            for (int c = 0; c < 8; c++) Q[c] = *(const float4*)(qrow + c * 4);
        }

        float mloc = -1e30f;
        for (int kj = k0r; kj < k1r; kj++) {
            const float* krow = Ks + kj * 36;
            float p0 = 0.f, p1 = 0.f, p2 = 0.f, p3 = 0.f;
            #pragma unroll
            for (int c = 0; c < 2; c++) {
                float4 k0 = *(const float4*)(krow + (c * 4 + 0) * 4);
                float4 k1 = *(const float4*)(krow + (c * 4 + 1) * 4);
                float4 k2 = *(const float4*)(krow + (c * 4 + 2) * 4);
                float4 k3 = *(const float4*)(krow + (c * 4 + 3) * 4);
                float4 q0v = Q[c * 4 + 0], q1v = Q[c * 4 + 1];
                float4 q2v = Q[c * 4 + 2], q3v = Q[c * 4 + 3];
                p0 = fmaf(q0v.x, k0.x, fmaf(q0v.y, k0.y,
                     fmaf(q0v.z, k0.z, fmaf(q0v.w, k0.w, p0))));
                p1 = fmaf(q1v.x, k1.x, fmaf(q1v.y, k1.y,
                     fmaf(q1v.z, k1.z, fmaf(q1v.w, k1.w, p1))));
                p2 = fmaf(q2v.x, k2.x, fmaf(q2v.y, k2.y,
                     fmaf(q2v.z, k2.z, fmaf(q2v.w, k2.w, p2))));
                p3 = fmaf(q3v.x, k3.x, fmaf(q3v.y, k3.y,
                     fmaf(q3v.z, k3.z, fmaf(q3v.w, k3.w, p3))));
            }
            float dot = (p0 + p1) + (p2 + p3);
            size_t off = (size_t)kj * LTOK + qglob;
            float s = mT[off] ? -1e30f : fmaf(dot, QSCALE, bias_h[off]);
            mloc = fmaxf(mloc, s);
            SsT[kj * 64 + qt] = s;
        }
        Red[r * 64 + qt] = mloc;
        __syncthreads();

        if (tid < 64) {
            float m = Red[tid];
            #pragma unroll
            for (int rr = 1; rr < 8; rr++) m = fmaxf(m, Red[rr * 64 + tid]);
            Mf[tid] = m;
        }
        __syncthreads();

        {
            float mq = Mf[qt];
            float ssum = 0.f;
            for (int kj = k0r; kj < k1r; kj++) {
                float p = __expf(SsT[kj * 64 + qt] - mq);
                SsT[kj * 64 + qt] = p;
                ssum += p;
            }
            Red[r * 64 + qt] = ssum;
        }
        __syncthreads();

        if (tid < 64) {
            float s = Red[tid];
            #pragma unroll
            for (int rr = 1; rr < 8; rr++) s += Red[rr * 64 + tid];
            Sf[tid] = 1.f / s;
        }
        __syncthreads();

        if (tid < 128) {
            int qgp = tid >> 3;
            int cg  = tid & 7;
            float4 a0 = make_float4(0.f, 0.f, 0.f, 0.f);
            float4 a1 = make_float4(0.f, 0.f, 0.f, 0.f);
            float4 a2 = make_float4(0.f, 0.f, 0.f, 0.f);
            float4 a3 = make_float4(0.f, 0.f, 0.f, 0.f);
            const float* sp = SsT + qgp * 4;
            const float* vp = Vs + cg * 4;
            #pragma unroll 4
            for (int j = 0; j < LTOK; j++) {
                float4 pv = *(const float4*)(sp + j * 64);
                float4 vv = *(const float4*)(vp + j * 36);
                a0.x = fmaf(pv.x, vv.x, a0.x);
                a0.y = fmaf(pv.x, vv.y, a0.y);
                a0.z = fmaf(pv.x, vv.z, a0.z);
                a0.w = fmaf(pv.x, vv.w, a0.w);
                a1.x = fmaf(pv.y, vv.x, a1.x);
                a1.y = fmaf(pv.y, vv.y, a1.y);
                a1.z = fmaf(pv.y, vv.z, a1.z);
                a1.w = fmaf(pv.y, vv.w, a1.w);
                a2.x = fmaf(pv.z, vv.x, a2.x);
                a2.y = fmaf(pv.z, vv.y, a2.y);
                a2.z = fmaf(pv.z, vv.z, a2.z);
                a2.w = fmaf(pv.z, vv.w, a2.w);
                a3.x = fmaf(pv.w, vv.x, a3.x);
                a3.y = fmaf(pv.w, vv.y, a3.y);
                a3.z = fmaf(pv.w, vv.z, a3.z);
                a3.w = fmaf(pv.w, vv.w, a3.w);
            }
            float4 accs[4] = {a0, a1, a2, a3};
            #pragma unroll
            for (int i = 0; i < 4; i++) {
                int qi = qgp * 4 + i;
                if (qi < qn) {
                    float inv = Sf[qi];
                    float4 o = make_float4(accs[i].x * inv, accs[i].y * inv,
                                           accs[i].z * inv, accs[i].w * inv);
                    float* og = g_ao + ((size_t)(n * LTOK + q0 + qi)) * DIMM
                                + h * HEADD + cg * 4;
                    *(float4*)og = o;
                }
            }
        }
        __syncthreads();
    }
}

// ======================================================================
extern "C" void kernel_launch(void* const* d_in, const int* in_sizes, int n_in,
                              void* d_out, int out_size)
{
    const float *x = nullptr, *qkvw = nullptr, *tbl = nullptr;
    const float *pw = nullptr, *pb = nullptr;
    const void* mask = nullptr;
    const int* ridx = nullptr;
    for (int i = 0; i < n_in; i++) {
        switch (in_sizes[i]) {
            case 8429568:  x    = (const float*)d_in[i]; break;
            case 442368:   qkvw = (const float*)d_in[i]; break;
            case 26364:    tbl  = (const float*)d_in[i]; break;
            case 147456:   pw   = (const float*)d_in[i]; break;
            case 384:      pb   = (const float*)d_in[i]; break;
            case 7530496:  mask = d_in[i]; break;
            case 117649:   ridx = (const int*)d_in[i]; break;
        }
    }
    if (n_in >= 7) {
        if (!x)    x    = (const float*)d_in[0];
        if (!qkvw) qkvw = (const float*)d_in[1];
        if (!tbl)  tbl  = (const float*)d_in[2];
        if (!pw)   pw   = (const float*)d_in[3];
        if (!pb)   pb   = (const float*)d_in[4];
        if (!mask) mask = d_in[5];
        if (!ridx) ridx = (const int*)d_in[6];
    }

    // 0) mask dtype detection
    detect_mask_kernel<<<1, 256>>>((const unsigned int*)mask);

    // 1) merged prep (maskT for 64 windows + biasT)
    prep_kernel<<<dim3(11, 11, NWIN + 1), dim3(32, 32)>>>(mask, tbl, ridx);

    // 2) QKV projection (tf32 tensor cores) + scatter
    mm_tf32_kernel<<<dim3(172, 18), 256>>>(x, qkvw, MROWS, 3 * DIMM, DIMM, 1,
                                           nullptr, nullptr);

    // 3) fused attention  (launch index 3 -> captured by ncu)
    size_t smem = (size_t)(LTOK * 36 * 2 + LTOK * 64 + 8 * 64 + 128)
                  * sizeof(float);
    cudaFuncSetAttribute(attn_kernel,
                         cudaFuncAttributeMaxDynamicSharedMemorySize, (int)smem);
    attn_kernel<<<NWIN * NHEAD, 512, smem>>>();

    // 4) output projection (tf32 tensor cores) + bias
    mm_tf32_kernel<<<dim3(172, 6), 256>>>(nullptr, pw, MROWS, DIMM, DIMM, 0,
                                          (float*)d_out, pb);
}

// round 10
// speedup vs baseline: 1.2385x; 1.1889x over previous
#include <cuda_runtime.h>

#define NWIN  64
#define NHEAD 12
#define LTOK  343
#define HEADD 32
#define DIMM  384
#define TBLN  2197
#define L2TOK (LTOK*LTOK)
#define QSCALE 0.17677669529663687f   // 32^-0.5
#define MROWS (NWIN*LTOK)             // 21952

// -------- scratch (static device globals; no runtime allocation) --------
__device__ __align__(16) float g_q[(size_t)NWIN*NHEAD*LTOK*HEADD];
__device__ __align__(16) float g_k[(size_t)NWIN*NHEAD*LTOK*HEADD];
__device__ __align__(16) float g_v[(size_t)NWIN*NHEAD*LTOK*HEADD];
__device__ __align__(16) float g_ao[(size_t)MROWS*DIMM];
__device__ __align__(16) float g_biasT[(size_t)NHEAD*L2TOK];        // [h][j][i]
__device__ __align__(16) unsigned char g_maskT[(size_t)NWIN*L2TOK]; // [n][j][i]
__device__ int g_mask_mode;   // 0 = 1-byte elements, 1 = 4-byte elements

// ======================================================================
__global__ void detect_mask_kernel(const unsigned int* __restrict__ m)
{
    __shared__ int s_not01, s_notf;
    if (threadIdx.x == 0) { s_not01 = 0; s_notf = 0; }
    __syncthreads();
    int bad01 = 0, badf = 0;
    for (int i = threadIdx.x; i < 4096; i += 256) {
        unsigned int w = m[i];
        if (w > 1u) bad01 = 1;
        if (w != 0u && w != 0x3F800000u) badf = 1;
    }
    if (bad01) atomicOr(&s_not01, 1);
    if (badf)  atomicOr(&s_notf, 1);
    __syncthreads();
    if (threadIdx.x == 0)
        g_mask_mode = (!s_not01 || !s_notf) ? 1 : 0;
}

// ======================================================================
// Merged prep: z in [0,64): maskT transpose; z == 64: biasT gather-transpose
// ======================================================================
__global__ void prep_kernel(const void* __restrict__ mask,
                            const float* __restrict__ table,
                            const int* __restrict__ rel_idx)
{
    const int tx = threadIdx.x, ty = threadIdx.y;
    const int i0 = blockIdx.x * 32, j0 = blockIdx.y * 32;
    const int z  = blockIdx.z;

    if (z < NWIN) {
        __shared__ unsigned char mt[32][33];
        const int mmode = g_mask_mode;
        int i = i0 + ty, j = j0 + tx;
        if (i < LTOK && j < LTOK) {
            size_t src = (size_t)z * L2TOK + (size_t)i * LTOK + j;
            bool mm = mmode ? (((const unsigned int*)mask)[src] != 0u)
                            : (((const unsigned char*)mask)[src] != 0);
            mt[ty][tx] = mm ? 1 : 0;
        }
        __syncthreads();
        int oj = j0 + ty, oi = i0 + tx;
        if (oj < LTOK && oi < LTOK)
            g_maskT[(size_t)z * L2TOK + (size_t)oj * LTOK + oi] = mt[tx][ty];
    } else {
        __shared__ int it[32][33];
        int i = i0 + ty, j = j0 + tx;
        if (i < LTOK && j < LTOK)
            it[ty][tx] = rel_idx[(size_t)i * LTOK + j];
        __syncthreads();
        int oj = j0 + ty, oi = i0 + tx;
        if (oj < LTOK && oi < LTOK) {
            int idx = it[tx][ty];
            const float* trow = table + (size_t)idx * NHEAD;
            size_t dst = (size_t)oj * LTOK + oi;
            #pragma unroll
            for (int h = 0; h < NHEAD; h++)
                g_biasT[(size_t)h * L2TOK + dst] = trow[h];
        }
    }
}

// ======================================================================
// tf32 helpers
// ======================================================================
__device__ __forceinline__ unsigned f2tf32(float f)
{
    unsigned r;
    asm("cvt.rna.tf32.f32 %0, %1;" : "=r"(r) : "f"(f));
    return r;
}

__device__ __forceinline__ void mma_tf32(float c[4], const unsigned a[4],
                                         const unsigned b[2])
{
    asm volatile(
        "mma.sync.aligned.m16n8k8.row.col.f32.tf32.tf32.f32 "
        "{%0,%1,%2,%3}, {%4,%5,%6,%7}, {%8,%9}, {%0,%1,%2,%3};"
        : "+f"(c[0]), "+f"(c[1]), "+f"(c[2]), "+f"(c[3])
        : "r"(a[0]), "r"(a[1]), "r"(a[2]), "r"(a[3]),
          "r"(b[0]), "r"(b[1]));
}

// ======================================================================
// tf32 tensor-core GEMM (round-7/9 version).
// ======================================================================
__global__ __launch_bounds__(256)
void mm_tf32_kernel(const float* __restrict__ Ain, const float* __restrict__ B,
                    int M, int N, int K, int mode,
                    float* __restrict__ C, const float* __restrict__ bias)
{
    __shared__ unsigned As[128][18];
    __shared__ unsigned Bs[16][72];

    const float* A = (mode == 0) ? g_ao : Ain;
    const int tid  = threadIdx.x;
    const int warp = tid >> 5, lane = tid & 31;
    const int wm   = warp & 3;
    const int wn   = warp >> 2;
    const int gid  = lane >> 2, tig = lane & 3;
    const int bm   = blockIdx.x * 128, bn = blockIdx.y * 64;

    float c[2][4][4];
    #pragma unroll
    for (int mt = 0; mt < 2; mt++)
        #pragma unroll
        for (int nt = 0; nt < 4; nt++)
            #pragma unroll
            for (int e = 0; e < 4; e++) c[mt][nt][e] = 0.f;

    for (int k0 = 0; k0 < K; k0 += 16) {
        #pragma unroll
        for (int i = 0; i < 2; i++) {
            int t  = tid + i * 256;
            int m  = t >> 2;
            int c4 = (t & 3) << 2;
            int gr = bm + m;
            float4 v = make_float4(0.f, 0.f, 0.f, 0.f);
            if (gr < M) v = *(const float4*)(A + (size_t)gr * K + k0 + c4);
            As[m][c4 + 0] = f2tf32(v.x);
            As[m][c4 + 1] = f2tf32(v.y);
            As[m][c4 + 2] = f2tf32(v.z);
            As[m][c4 + 3] = f2tf32(v.w);
        }
        {
            int kr = tid >> 4;
            int c4 = (tid & 15) << 2;
            float4 v = *(const float4*)(B + (size_t)(k0 + kr) * N + bn + c4);
            Bs[kr][c4 + 0] = f2tf32(v.x);
            Bs[kr][c4 + 1] = f2tf32(v.y);
            Bs[kr][c4 + 2] = f2tf32(v.z);
            Bs[kr][c4 + 3] = f2tf32(v.w);
        }
        __syncthreads();

        #pragma unroll
        for (int ks = 0; ks < 16; ks += 8) {
            unsigned af[2][4], bf[4][2];
            #pragma unroll
            for (int mt = 0; mt < 2; mt++) {
                int mr = wm * 32 + mt * 16 + gid;
                af[mt][0] = As[mr][ks + tig];
                af[mt][1] = As[mr + 8][ks + tig];
                af[mt][2] = As[mr][ks + tig + 4];
                af[mt][3] = As[mr + 8][ks + tig + 4];
            }
            #pragma unroll
            for (int nt = 0; nt < 4; nt++) {
                int nc = wn * 32 + nt * 8 + gid;
                bf[nt][0] = Bs[ks + tig][nc];
                bf[nt][1] = Bs[ks + tig + 4][nc];
            }
            #pragma unroll
            for (int mt = 0; mt < 2; mt++)
                #pragma unroll
                for (int nt = 0; nt < 4; nt++)
                    mma_tf32(c[mt][nt], af[mt], bf[nt]);
        }
        __syncthreads();
    }

    #pragma unroll
    for (int mt = 0; mt < 2; mt++) {
        int r0 = bm + wm * 32 + mt * 16 + gid;
        int r1 = r0 + 8;
        if (mode == 0) {
            #pragma unroll
            for (int nt = 0; nt < 4; nt++) {
                int col = bn + wn * 32 + nt * 8 + tig * 2;
                float bx = bias[col], by = bias[col + 1];
                if (r0 < M) {
                    float2 o = make_float2(c[mt][nt][0] + bx, c[mt][nt][1] + by);
                    *(float2*)(C + (size_t)r0 * N + col) = o;
                }
                if (r1 < M) {
                    float2 o = make_float2(c[mt][nt][2] + bx, c[mt][nt][3] + by);
                    *(float2*)(C + (size_t)r1 * N + col) = o;
                }
            }
        } else {
            int n0 = r0 / LTOK, l0 = r0 - n0 * LTOK;
            int n1 = r1 / LTOK, l1 = r1 - n1 * LTOK;
            #pragma unroll
            for (int nt = 0; nt < 4; nt++) {
                int colb = bn + wn * 32 + nt * 8 + tig * 2;
                #pragma unroll
                for (int e = 0; e < 4; e++) {
                    int row = (e < 2) ? r0 : r1;
                    if (row >= M) continue;
                    int nn  = (e < 2) ? n0 : n1;
                    int ll  = (e < 2) ? l0 : l1;
                    int col = colb + (e & 1);
                    int s   = col / DIMM;
                    int rem = col - s * DIMM;
                    int hh  = rem >> 5;
                    int cc  = rem & 31;
                    float* dst = (s == 0) ? g_q : ((s == 1) ? g_k : g_v);
                    dst[(((size_t)(nn * NHEAD + hh)) * LTOK + ll) * HEADD + cc]
                        = c[mt][nt][e];
                }
            }
        }
    }
}

// ======================================================================
// Tensor-core fused window attention. Block(512) = 16 warps per (win, head).
// smem (words): Qs[64][36] | Kt[32][360] | Vs[344][40] | Sp[64][356]
//               Red[4][64] | Mf[64] | Sf[64]   = 50752 words = 203 KB
// ======================================================================
__global__ __launch_bounds__(512)
void attn_kernel()
{
    extern __shared__ unsigned smu[];
    unsigned* Qs  = smu;                  // [64][36]  tf32
    unsigned* Kt  = smu + 2304;           // [c][j] stride 360, tf32
    unsigned* Vs  = smu + 13824;          // [j][c] stride 40, tf32
    float*    Sp  = (float*)(smu + 27584);// [64][356] scores -> tf32 probs
    float*    Red = (float*)(smu + 50368);// [4][64]
    float*    Mf  = Red + 256;            // [64]
    float*    Sf  = Mf + 64;              // [64]

    const int tid  = threadIdx.x;
    const int warp = tid >> 5;
    const int lane = tid & 31;
    const int gid  = lane >> 2;   // 0..7
    const int tig  = lane & 3;    // 0..3
    const int bh   = blockIdx.x;
    const int n    = bh / NHEAD;
    const int h    = bh - n * NHEAD;
    const int wm   = warp & 3;    // m16-tile
    const int wc   = warp >> 2;   // column group
    const int m0   = wm * 16;

    const float* bias_h = g_biasT + (size_t)h * L2TOK;
    const unsigned char* mT = g_maskT + (size_t)n * L2TOK;

    // ---- load K transposed + V, tf32 ----
    const float* kg = g_k + (size_t)bh * LTOK * HEADD;
    const float* vg = g_v + (size_t)bh * LTOK * HEADD;
    for (int i = tid; i < LTOK * 8; i += 512) {
        int j = i >> 3, c4 = (i & 7) << 2;
        float4 kv = *(const float4*)(kg + (size_t)i * 4);
        Kt[(c4 + 0) * 360 + j] = f2tf32(kv.x);
        Kt[(c4 + 1) * 360 + j] = f2tf32(kv.y);
        Kt[(c4 + 2) * 360 + j] = f2tf32(kv.z);
        Kt[(c4 + 3) * 360 + j] = f2tf32(kv.w);
        float4 vv = *(const float4*)(vg + (size_t)i * 4);
        uint4 w;
        w.x = f2tf32(vv.x); w.y = f2tf32(vv.y);
        w.z = f2tf32(vv.z); w.w = f2tf32(vv.w);
        *(uint4*)&Vs[j * 40 + c4] = w;
    }
    if (tid < 32) Kt[tid * 360 + 343] = 0;                 // pad col
    if (tid >= 64 && tid < 96) Vs[343 * 40 + (tid - 64)] = 0; // pad row
    __syncthreads();

    const float* qg = g_q + (size_t)bh * LTOK * HEADD;

    for (int q0 = 0; q0 < LTOK; q0 += 64) {
        const int qn = min(64, LTOK - q0);

        // Q tile -> tf32 smem
        for (int i = tid; i < qn * 8; i += 512) {
            int row = i >> 3, c4 = (i & 7) << 2;
            float4 v = *(const float4*)(qg + (size_t)(q0 + row) * HEADD + c4);
            uint4 w;
            w.x = f2tf32(v.x); w.y = f2tf32(v.y);
            w.z = f2tf32(v.z); w.w = f2tf32(v.w);
            *(uint4*)&Qs[row * 36 + c4] = w;
        }
        __syncthreads();

        // ---- scores: S[q][j] = Q . K^T (tf32 mma) + bias/mask, online max --
        unsigned af[4][4];
        #pragma unroll
        for (int ks = 0; ks < 4; ks++) {
            int kk = ks * 8;
            af[ks][0] = Qs[(m0 + gid) * 36 + kk + tig];
            af[ks][1] = Qs[(m0 + gid + 8) * 36 + kk + tig];
            af[ks][2] = Qs[(m0 + gid) * 36 + kk + tig + 4];
            af[ks][3] = Qs[(m0 + gid + 8) * 36 + kk + tig + 4];
        }
        const int q_lo = q0 + m0 + gid;
        const int q_hi = q_lo + 8;
        float mx0 = -1e30f, mx1 = -1e30f;

        for (int jb = wc; jb < 43; jb += 4) {
            int n0 = jb * 8;
            float cc[4] = {0.f, 0.f, 0.f, 0.f};
            #pragma unroll
            for (int ks = 0; ks < 4; ks++) {
                int kk = ks * 8;
                unsigned bf[2];
                bf[0] = Kt[(kk + tig) * 360 + n0 + gid];
                bf[1] = Kt[(kk + tig + 4) * 360 + n0 + gid];
                mma_tf32(cc, af[ks], bf);
            }
            int j0 = n0 + tig * 2;
            float s0 = -1e30f, s1 = -1e30f, s2 = -1e30f, s3 = -1e30f;
            if (q_lo < LTOK) {
                size_t o0 = (size_t)j0 * LTOK + q_lo;
                if (j0 < LTOK && !mT[o0])
                    s0 = fmaf(cc[0], QSCALE, bias_h[o0]);
                size_t o1 = o0 + LTOK;
                if (j0 + 1 < LTOK && !mT[o1])
                    s1 = fmaf(cc[1], QSCALE, bias_h[o1]);
            }
            if (q_hi < LTOK) {
                size_t o2 = (size_t)j0 * LTOK + q_hi;
                if (j0 < LTOK && !mT[o2])
                    s2 = fmaf(cc[2], QSCALE, bias_h[o2]);
                size_t o3 = o2 + LTOK;
                if (j0 + 1 < LTOK && !mT[o3])
                    s3 = fmaf(cc[3], QSCALE, bias_h[o3]);
            }
            mx0 = fmaxf(mx0, fmaxf(s0, s1));
            mx1 = fmaxf(mx1, fmaxf(s2, s3));
            *(float2*)&Sp[(m0 + gid) * 356 + j0]     = make_float2(s0, s1);
            *(float2*)&Sp[(m0 + gid + 8) * 356 + j0] = make_float2(s2, s3);
        }
        mx0 = fmaxf(mx0, __shfl_xor_sync(0xffffffffu, mx0, 1));
        mx0 = fmaxf(mx0, __shfl_xor_sync(0xffffffffu, mx0, 2));
        mx1 = fmaxf(mx1, __shfl_xor_sync(0xffffffffu, mx1, 1));
        mx1 = fmaxf(mx1, __shfl_xor_sync(0xffffffffu, mx1, 2));
        if (tig == 0) {
            Red[wc * 64 + m0 + gid]     = mx0;
            Red[wc * 64 + m0 + gid + 8] = mx1;
        }
        __syncthreads();
        if (tid < 64) {
            float m = Red[tid];
            m = fmaxf(m, Red[64 + tid]);
            m = fmaxf(m, Red[128 + tid]);
            m = fmaxf(m, Red[192 + tid]);
            Mf[tid] = m;
        }
        __syncthreads();

        // ---- exp, tf32-round probs in place, partial sums ----
        {
            float M0 = Mf[m0 + gid], M1 = Mf[m0 + gid + 8];
            float sm0 = 0.f, sm1 = 0.f;
            for (int jb = wc; jb < 43; jb += 4) {
                int j0 = jb * 8 + tig * 2;
                float* r0 = &Sp[(m0 + gid) * 356 + j0];
                float* r1 = &Sp[(m0 + gid + 8) * 356 + j0];
                float2 v0 = *(float2*)r0;
                float2 v1 = *(float2*)r1;
                unsigned u00 = f2tf32(__expf(v0.x - M0));
                unsigned u01 = f2tf32(__expf(v0.y - M0));
                unsigned u10 = f2tf32(__expf(v1.x - M1));
                unsigned u11 = f2tf32(__expf(v1.y - M1));
                sm0 += __uint_as_float(u00) + __uint_as_float(u01);
                sm1 += __uint_as_float(u10) + __uint_as_float(u11);
                ((unsigned*)r0)[0] = u00; ((unsigned*)r0)[1] = u01;
                ((unsigned*)r1)[0] = u10; ((unsigned*)r1)[1] = u11;
            }
            sm0 += __shfl_xor_sync(0xffffffffu, sm0, 1);
            sm0 += __shfl_xor_sync(0xffffffffu, sm0, 2);
            sm1 += __shfl_xor_sync(0xffffffffu, sm1, 1);
            sm1 += __shfl_xor_sync(0xffffffffu, sm1, 2);
            if (tig == 0) {
                Red[wc * 64 + m0 + gid]     = sm0;
                Red[wc * 64 + m0 + gid + 8] = sm1;
            }
        }
        __syncthreads();
        if (tid < 64) {
            float s = Red[tid] + Red[64 + tid] + Red[128 + tid]
                    + Red[192 + tid];
            Sf[tid] = 1.f / s;
        }
        __syncthreads();

        // ---- AV: out[q][c] = P . V (tf32 mma), warp = (wm, wc) ----
        {
            const unsigned* Pb = (const unsigned*)Sp;
            float cv[4] = {0.f, 0.f, 0.f, 0.f};
            for (int k8 = 0; k8 < 43; k8++) {
                int kk = k8 * 8;
                unsigned a2[4], b2[2];
                a2[0] = Pb[(m0 + gid) * 356 + kk + tig];
                a2[1] = Pb[(m0 + gid + 8) * 356 + kk + tig];
                a2[2] = Pb[(m0 + gid) * 356 + kk + tig + 4];
                a2[3] = Pb[(m0 + gid + 8) * 356 + kk + tig + 4];
                b2[0] = Vs[(kk + tig) * 40 + wc * 8 + gid];
                b2[1] = Vs[(kk + tig + 4) * 40 + wc * 8 + gid];
                mma_tf32(cv, a2, b2);
            }
            int cc = wc * 8 + tig * 2;
            if (q_lo < LTOK) {
                float inv = Sf[m0 + gid];
                float2 o = make_float2(cv[0] * inv, cv[1] * inv);
                *(float2*)(g_ao + ((size_t)(n * LTOK + q_lo)) * DIMM
                           + h * HEADD + cc) = o;
            }
            if (q_hi < LTOK) {
                float inv = Sf[m0 + gid + 8];
                float2 o = make_float2(cv[2] * inv, cv[3] * inv);
                *(float2*)(g_ao + ((size_t)(n * LTOK + q_hi)) * DIMM
                           + h * HEADD + cc) = o;
            }
        }
        __syncthreads();
    }
}

// ======================================================================
extern "C" void kernel_launch(void* const* d_in, const int* in_sizes, int n_in,
                              void* d_out, int out_size)
{
    const float *x = nullptr, *qkvw = nullptr, *tbl = nullptr;
    const float *pw = nullptr, *pb = nullptr;
    const void* mask = nullptr;
    const int* ridx = nullptr;
    for (int i = 0; i < n_in; i++) {
        switch (in_sizes[i]) {
            case 8429568:  x    = (const float*)d_in[i]; break;
            case 442368:   qkvw = (const float*)d_in[i]; break;
            case 26364:    tbl  = (const float*)d_in[i]; break;
            case 147456:   pw   = (const float*)d_in[i]; break;
            case 384:      pb   = (const float*)d_in[i]; break;
            case 7530496:  mask = d_in[i]; break;
            case 117649:   ridx = (const int*)d_in[i]; break;
        }
    }
    if (n_in >= 7) {
        if (!x)    x    = (const float*)d_in[0];
        if (!qkvw) qkvw = (const float*)d_in[1];
        if (!tbl)  tbl  = (const float*)d_in[2];
        if (!pw)   pw   = (const float*)d_in[3];
        if (!pb)   pb   = (const float*)d_in[4];
        if (!mask) mask = d_in[5];
        if (!ridx) ridx = (const int*)d_in[6];
    }

    // 0) mask dtype detection
    detect_mask_kernel<<<1, 256>>>((const unsigned int*)mask);

    // 1) merged prep (maskT + biasT)
    prep_kernel<<<dim3(11, 11, NWIN + 1), dim3(32, 32)>>>(mask, tbl, ridx);

    // 2) QKV projection (tf32 tensor cores) + scatter
    mm_tf32_kernel<<<dim3(172, 18), 256>>>(x, qkvw, MROWS, 3 * DIMM, DIMM, 1,
                                           nullptr, nullptr);

    // 3) tensor-core fused attention (launch #3 -> ncu capture)
    size_t smem = 50752u * sizeof(unsigned);   // 203 KB
    cudaFuncSetAttribute(attn_kernel,
                         cudaFuncAttributeMaxDynamicSharedMemorySize, (int)smem);
    attn_kernel<<<NWIN * NHEAD, 512, smem>>>();

    // 4) output projection (tf32 tensor cores) + bias
    mm_tf32_kernel<<<dim3(172, 6), 256>>>(nullptr, pw, MROWS, DIMM, DIMM, 0,
                                          (float*)d_out, pb);
}

// round 11
// speedup vs baseline: 1.5501x; 1.2516x over previous
#include <cuda_runtime.h>

#define NWIN  64
#define NHEAD 12
#define LTOK  343
#define HEADD 32
#define DIMM  384
#define TBLN  2197
#define L2TOK (LTOK*LTOK)
#define QSCALE 0.17677669529663687f   // 32^-0.5
#define MROWS (NWIN*LTOK)             // 21952

// -------- scratch (static device globals; no runtime allocation) --------
__device__ __align__(16) float g_q[(size_t)NWIN*NHEAD*LTOK*HEADD];
__device__ __align__(16) float g_k[(size_t)NWIN*NHEAD*LTOK*HEADD];
__device__ __align__(16) float g_v[(size_t)NWIN*NHEAD*LTOK*HEADD];
__device__ __align__(16) float g_ao[(size_t)MROWS*DIMM];
__device__ __align__(16) float g_biasT[(size_t)NHEAD*L2TOK];        // [h][j][i]
__device__ __align__(16) unsigned char g_maskT[(size_t)NWIN*L2TOK]; // [n][j][i]
__device__ int g_mask_mode;   // 0 = 1-byte elements, 1 = 4-byte elements

// ======================================================================
__global__ void detect_mask_kernel(const unsigned int* __restrict__ m)
{
    __shared__ int s_not01, s_notf;
    if (threadIdx.x == 0) { s_not01 = 0; s_notf = 0; }
    __syncthreads();
    int bad01 = 0, badf = 0;
    for (int i = threadIdx.x; i < 4096; i += 256) {
        unsigned int w = m[i];
        if (w > 1u) bad01 = 1;
        if (w != 0u && w != 0x3F800000u) badf = 1;
    }
    if (bad01) atomicOr(&s_not01, 1);
    if (badf)  atomicOr(&s_notf, 1);
    __syncthreads();
    if (threadIdx.x == 0)
        g_mask_mode = (!s_not01 || !s_notf) ? 1 : 0;
}

// ======================================================================
// Merged prep: z in [0,64): maskT transpose; z == 64: biasT gather-transpose
// ======================================================================
__global__ void prep_kernel(const void* __restrict__ mask,
                            const float* __restrict__ table,
                            const int* __restrict__ rel_idx)
{
    const int tx = threadIdx.x, ty = threadIdx.y;
    const int i0 = blockIdx.x * 32, j0 = blockIdx.y * 32;
    const int z  = blockIdx.z;

    if (z < NWIN) {
        __shared__ unsigned char mt[32][33];
        const int mmode = g_mask_mode;
        int i = i0 + ty, j = j0 + tx;
        if (i < LTOK && j < LTOK) {
            size_t src = (size_t)z * L2TOK + (size_t)i * LTOK + j;
            bool mm = mmode ? (((const unsigned int*)mask)[src] != 0u)
                            : (((const unsigned char*)mask)[src] != 0);
            mt[ty][tx] = mm ? 1 : 0;
        }
        __syncthreads();
        int oj = j0 + ty, oi = i0 + tx;
        if (oj < LTOK && oi < LTOK)
            g_maskT[(size_t)z * L2TOK + (size_t)oj * LTOK + oi] = mt[tx][ty];
    } else {
        __shared__ int it[32][33];
        int i = i0 + ty, j = j0 + tx;
        if (i < LTOK && j < LTOK)
            it[ty][tx] = rel_idx[(size_t)i * LTOK + j];
        __syncthreads();
        int oj = j0 + ty, oi = i0 + tx;
        if (oj < LTOK && oi < LTOK) {
            int idx = it[tx][ty];
            const float* trow = table + (size_t)idx * NHEAD;
            size_t dst = (size_t)oj * LTOK + oi;
            #pragma unroll
            for (int h = 0; h < NHEAD; h++)
                g_biasT[(size_t)h * L2TOK + dst] = trow[h];
        }
    }
}

// ======================================================================
// tf32 helpers
// ======================================================================
__device__ __forceinline__ unsigned f2tf32(float f)
{
    unsigned r;
    asm("cvt.rna.tf32.f32 %0, %1;" : "=r"(r) : "f"(f));
    return r;
}

__device__ __forceinline__ void mma_tf32(float c[4], const unsigned a[4],
                                         const unsigned b[2])
{
    asm volatile(
        "mma.sync.aligned.m16n8k8.row.col.f32.tf32.tf32.f32 "
        "{%0,%1,%2,%3}, {%4,%5,%6,%7}, {%8,%9}, {%0,%1,%2,%3};"
        : "+f"(c[0]), "+f"(c[1]), "+f"(c[2]), "+f"(c[3])
        : "r"(a[0]), "r"(a[1]), "r"(a[2]), "r"(a[3]),
          "r"(b[0]), "r"(b[1]));
}

// ======================================================================
// tf32 tensor-core GEMM (round-7/9 version).
// ======================================================================
__global__ __launch_bounds__(256)
void mm_tf32_kernel(const float* __restrict__ Ain, const float* __restrict__ B,
                    int M, int N, int K, int mode,
                    float* __restrict__ C, const float* __restrict__ bias)
{
    __shared__ unsigned As[128][18];
    __shared__ unsigned Bs[16][72];

    const float* A = (mode == 0) ? g_ao : Ain;
    const int tid  = threadIdx.x;
    const int warp = tid >> 5, lane = tid & 31;
    const int wm   = warp & 3;
    const int wn   = warp >> 2;
    const int gid  = lane >> 2, tig = lane & 3;
    const int bm   = blockIdx.x * 128, bn = blockIdx.y * 64;

    float c[2][4][4];
    #pragma unroll
    for (int mt = 0; mt < 2; mt++)
        #pragma unroll
        for (int nt = 0; nt < 4; nt++)
            #pragma unroll
            for (int e = 0; e < 4; e++) c[mt][nt][e] = 0.f;

    for (int k0 = 0; k0 < K; k0 += 16) {
        #pragma unroll
        for (int i = 0; i < 2; i++) {
            int t  = tid + i * 256;
            int m  = t >> 2;
            int c4 = (t & 3) << 2;
            int gr = bm + m;
            float4 v = make_float4(0.f, 0.f, 0.f, 0.f);
            if (gr < M) v = *(const float4*)(A + (size_t)gr * K + k0 + c4);
            As[m][c4 + 0] = f2tf32(v.x);
            As[m][c4 + 1] = f2tf32(v.y);
            As[m][c4 + 2] = f2tf32(v.z);
            As[m][c4 + 3] = f2tf32(v.w);
        }
        {
            int kr = tid >> 4;
            int c4 = (tid & 15) << 2;
            float4 v = *(const float4*)(B + (size_t)(k0 + kr) * N + bn + c4);
            Bs[kr][c4 + 0] = f2tf32(v.x);
            Bs[kr][c4 + 1] = f2tf32(v.y);
            Bs[kr][c4 + 2] = f2tf32(v.z);
            Bs[kr][c4 + 3] = f2tf32(v.w);
        }
        __syncthreads();

        #pragma unroll
        for (int ks = 0; ks < 16; ks += 8) {
            unsigned af[2][4], bf[4][2];
            #pragma unroll
            for (int mt = 0; mt < 2; mt++) {
                int mr = wm * 32 + mt * 16 + gid;
                af[mt][0] = As[mr][ks + tig];
                af[mt][1] = As[mr + 8][ks + tig];
                af[mt][2] = As[mr][ks + tig + 4];
                af[mt][3] = As[mr + 8][ks + tig + 4];
            }
            #pragma unroll
            for (int nt = 0; nt < 4; nt++) {
                int nc = wn * 32 + nt * 8 + gid;
                bf[nt][0] = Bs[ks + tig][nc];
                bf[nt][1] = Bs[ks + tig + 4][nc];
            }
            #pragma unroll
            for (int mt = 0; mt < 2; mt++)
                #pragma unroll
                for (int nt = 0; nt < 4; nt++)
                    mma_tf32(c[mt][nt], af[mt], bf[nt]);
        }
        __syncthreads();
    }

    #pragma unroll
    for (int mt = 0; mt < 2; mt++) {
        int r0 = bm + wm * 32 + mt * 16 + gid;
        int r1 = r0 + 8;
        if (mode == 0) {
            #pragma unroll
            for (int nt = 0; nt < 4; nt++) {
                int col = bn + wn * 32 + nt * 8 + tig * 2;
                float bx = bias[col], by = bias[col + 1];
                if (r0 < M) {
                    float2 o = make_float2(c[mt][nt][0] + bx, c[mt][nt][1] + by);
                    *(float2*)(C + (size_t)r0 * N + col) = o;
                }
                if (r1 < M) {
                    float2 o = make_float2(c[mt][nt][2] + bx, c[mt][nt][3] + by);
                    *(float2*)(C + (size_t)r1 * N + col) = o;
                }
            }
        } else {
            int n0 = r0 / LTOK, l0 = r0 - n0 * LTOK;
            int n1 = r1 / LTOK, l1 = r1 - n1 * LTOK;
            #pragma unroll
            for (int nt = 0; nt < 4; nt++) {
                int colb = bn + wn * 32 + nt * 8 + tig * 2;
                #pragma unroll
                for (int e = 0; e < 4; e++) {
                    int row = (e < 2) ? r0 : r1;
                    if (row >= M) continue;
                    int nn  = (e < 2) ? n0 : n1;
                    int ll  = (e < 2) ? l0 : l1;
                    int col = colb + (e & 1);
                    int s   = col / DIMM;
                    int rem = col - s * DIMM;
                    int hh  = rem >> 5;
                    int cc  = rem & 31;
                    float* dst = (s == 0) ? g_q : ((s == 1) ? g_k : g_v);
                    dst[(((size_t)(nn * NHEAD + hh)) * LTOK + ll) * HEADD + cc]
                        = c[mt][nt][e];
                }
            }
        }
    }
}

// ======================================================================
// Tensor-core fused window attention v3: 1024 threads = 32 warps.
// warp = (wm 0..3, wg 0..7). Score/exp: columns split 8 ways.
// AV: k split across warp pairs (kh = wg>>2), partials in smem.
// smem words: Qs 2304 | Kt 11520 | Vs 13760 | Sp 22784 | Pp 4608
//             Red 512 | Mf 64 | Sf 64  = 55616 words = 222.5 KB
// ======================================================================
__global__ __launch_bounds__(1024, 1)
void attn_kernel()
{
    extern __shared__ unsigned smu[];
    unsigned* Qs  = smu;                   // [64][36]  tf32
    unsigned* Kt  = smu + 2304;            // [c][j] stride 360
    unsigned* Vs  = smu + 13824;           // [j][c] stride 40
    float*    Sp  = (float*)(smu + 27584); // [64][356]
    float*    Pp  = (float*)(smu + 50368); // [2][64][36] AV partials
    float*    Red = (float*)(smu + 54976); // [8][64]
    float*    Mf  = Red + 512;             // [64]
    float*    Sf  = Mf + 64;               // [64]

    const int tid  = threadIdx.x;
    const int warp = tid >> 5;
    const int lane = tid & 31;
    const int gid  = lane >> 2;
    const int tig  = lane & 3;
    const int bh   = blockIdx.x;
    const int n    = bh / NHEAD;
    const int h    = bh - n * NHEAD;
    const int wm   = warp & 3;     // m16-tile
    const int wg   = warp >> 2;    // 0..7
    const int m0   = wm * 16;

    const float* bias_h = g_biasT + (size_t)h * L2TOK;
    const unsigned char* mT = g_maskT + (size_t)n * L2TOK;

    // ---- load K transposed + V, tf32 ----
    const float* kg = g_k + (size_t)bh * LTOK * HEADD;
    const float* vg = g_v + (size_t)bh * LTOK * HEADD;
    for (int i = tid; i < LTOK * 8; i += 1024) {
        int j = i >> 3, c4 = (i & 7) << 2;
        float4 kv = *(const float4*)(kg + (size_t)i * 4);
        Kt[(c4 + 0) * 360 + j] = f2tf32(kv.x);
        Kt[(c4 + 1) * 360 + j] = f2tf32(kv.y);
        Kt[(c4 + 2) * 360 + j] = f2tf32(kv.z);
        Kt[(c4 + 3) * 360 + j] = f2tf32(kv.w);
        float4 vv = *(const float4*)(vg + (size_t)i * 4);
        uint4 w;
        w.x = f2tf32(vv.x); w.y = f2tf32(vv.y);
        w.z = f2tf32(vv.z); w.w = f2tf32(vv.w);
        *(uint4*)&Vs[j * 40 + c4] = w;
    }
    if (tid < 32) Kt[tid * 360 + 343] = 0;
    if (tid >= 64 && tid < 96) Vs[343 * 40 + (tid - 64)] = 0;
    __syncthreads();

    const float* qg = g_q + (size_t)bh * LTOK * HEADD;

    for (int q0 = 0; q0 < LTOK; q0 += 64) {
        const int qn = min(64, LTOK - q0);

        // Q tile -> tf32 smem
        for (int i = tid; i < qn * 8; i += 1024) {
            int row = i >> 3, c4 = (i & 7) << 2;
            float4 v = *(const float4*)(qg + (size_t)(q0 + row) * HEADD + c4);
            uint4 w;
            w.x = f2tf32(v.x); w.y = f2tf32(v.y);
            w.z = f2tf32(v.z); w.w = f2tf32(v.w);
            *(uint4*)&Qs[row * 36 + c4] = w;
        }
        __syncthreads();

        // ---- scores: warp (wm, wg), jb stride 8, 2 indep accumulators ----
        unsigned af[4][4];
        #pragma unroll
        for (int ks = 0; ks < 4; ks++) {
            int kk = ks * 8;
            af[ks][0] = Qs[(m0 + gid) * 36 + kk + tig];
            af[ks][1] = Qs[(m0 + gid + 8) * 36 + kk + tig];
            af[ks][2] = Qs[(m0 + gid) * 36 + kk + tig + 4];
            af[ks][3] = Qs[(m0 + gid + 8) * 36 + kk + tig + 4];
        }
        const int q_lo = q0 + m0 + gid;
        const int q_hi = q_lo + 8;
        float mx0 = -1e30f, mx1 = -1e30f;

        for (int jb = wg; jb < 43; jb += 8) {
            int n0 = jb * 8;
            float ca[4] = {0.f, 0.f, 0.f, 0.f};
            float cb[4] = {0.f, 0.f, 0.f, 0.f};
            {
                unsigned bf0[2], bf1[2];
                bf0[0] = Kt[(0 + tig) * 360 + n0 + gid];
                bf0[1] = Kt[(4 + tig) * 360 + n0 + gid];
                bf1[0] = Kt[(8 + tig) * 360 + n0 + gid];
                bf1[1] = Kt[(12 + tig) * 360 + n0 + gid];
                mma_tf32(ca, af[0], bf0);
                mma_tf32(cb, af[1], bf1);
                bf0[0] = Kt[(16 + tig) * 360 + n0 + gid];
                bf0[1] = Kt[(20 + tig) * 360 + n0 + gid];
                bf1[0] = Kt[(24 + tig) * 360 + n0 + gid];
                bf1[1] = Kt[(28 + tig) * 360 + n0 + gid];
                mma_tf32(ca, af[2], bf0);
                mma_tf32(cb, af[3], bf1);
            }
            float cc0 = ca[0] + cb[0], cc1 = ca[1] + cb[1];
            float cc2 = ca[2] + cb[2], cc3 = ca[3] + cb[3];

            int j0 = n0 + tig * 2;
            float s0 = -1e30f, s1 = -1e30f, s2 = -1e30f, s3 = -1e30f;
            if (q_lo < LTOK) {
                size_t o0 = (size_t)j0 * LTOK + q_lo;
                if (j0 < LTOK && !mT[o0])
                    s0 = fmaf(cc0, QSCALE, bias_h[o0]);
                size_t o1 = o0 + LTOK;
                if (j0 + 1 < LTOK && !mT[o1])
                    s1 = fmaf(cc1, QSCALE, bias_h[o1]);
            }
            if (q_hi < LTOK) {
                size_t o2 = (size_t)j0 * LTOK + q_hi;
                if (j0 < LTOK && !mT[o2])
                    s2 = fmaf(cc2, QSCALE, bias_h[o2]);
                size_t o3 = o2 + LTOK;
                if (j0 + 1 < LTOK && !mT[o3])
                    s3 = fmaf(cc3, QSCALE, bias_h[o3]);
            }
            mx0 = fmaxf(mx0, fmaxf(s0, s1));
            mx1 = fmaxf(mx1, fmaxf(s2, s3));
            *(float2*)&Sp[(m0 + gid) * 356 + j0]     = make_float2(s0, s1);
            *(float2*)&Sp[(m0 + gid + 8) * 356 + j0] = make_float2(s2, s3);
        }
        mx0 = fmaxf(mx0, __shfl_xor_sync(0xffffffffu, mx0, 1));
        mx0 = fmaxf(mx0, __shfl_xor_sync(0xffffffffu, mx0, 2));
        mx1 = fmaxf(mx1, __shfl_xor_sync(0xffffffffu, mx1, 1));
        mx1 = fmaxf(mx1, __shfl_xor_sync(0xffffffffu, mx1, 2));
        if (tig == 0) {
            Red[wg * 64 + m0 + gid]     = mx0;
            Red[wg * 64 + m0 + gid + 8] = mx1;
        }
        __syncthreads();
        if (tid < 64) {
            float m = Red[tid];
            #pragma unroll
            for (int rr = 1; rr < 8; rr++)
                m = fmaxf(m, Red[rr * 64 + tid]);
            Mf[tid] = m;
        }
        __syncthreads();

        // ---- exp, tf32 probs in place, partial sums ----
        {
            float M0 = Mf[m0 + gid], M1 = Mf[m0 + gid + 8];
            float sm0 = 0.f, sm1 = 0.f;
            for (int jb = wg; jb < 43; jb += 8) {
                int j0 = jb * 8 + tig * 2;
                float* r0 = &Sp[(m0 + gid) * 356 + j0];
                float* r1 = &Sp[(m0 + gid + 8) * 356 + j0];
                float2 v0 = *(float2*)r0;
                float2 v1 = *(float2*)r1;
                unsigned u00 = f2tf32(__expf(v0.x - M0));
                unsigned u01 = f2tf32(__expf(v0.y - M0));
                unsigned u10 = f2tf32(__expf(v1.x - M1));
                unsigned u11 = f2tf32(__expf(v1.y - M1));
                sm0 += __uint_as_float(u00) + __uint_as_float(u01);
                sm1 += __uint_as_float(u10) + __uint_as_float(u11);
                ((unsigned*)r0)[0] = u00; ((unsigned*)r0)[1] = u01;
                ((unsigned*)r1)[0] = u10; ((unsigned*)r1)[1] = u11;
            }
            sm0 += __shfl_xor_sync(0xffffffffu, sm0, 1);
            sm0 += __shfl_xor_sync(0xffffffffu, sm0, 2);
            sm1 += __shfl_xor_sync(0xffffffffu, sm1, 1);
            sm1 += __shfl_xor_sync(0xffffffffu, sm1, 2);
            if (tig == 0) {
                Red[wg * 64 + m0 + gid]     = sm0;
                Red[wg * 64 + m0 + gid + 8] = sm1;
            }
        }
        __syncthreads();
        if (tid < 64) {
            float s = 0.f;
            #pragma unroll
            for (int rr = 0; rr < 8; rr++) s += Red[rr * 64 + tid];
            Sf[tid] = 1.f / s;
        }
        __syncthreads();

        // ---- AV: warp (wm, wc=wg&3, kh=wg>>2); 2 indep chains per half ---
        {
            const unsigned* Pb = (const unsigned*)Sp;
            const int wc = wg & 3;
            const int kh = wg >> 2;
            const int kbeg = kh ? 22 : 0;
            const int kmid = kh ? 33 : 11;
            const int kend = kh ? 43 : 22;
            float cva[4] = {0.f, 0.f, 0.f, 0.f};
            float cvb[4] = {0.f, 0.f, 0.f, 0.f};
            for (int k8 = kbeg; k8 < kmid; k8++) {
                int kk = k8 * 8;
                unsigned a2[4], b2[2];
                a2[0] = Pb[(m0 + gid) * 356 + kk + tig];
                a2[1] = Pb[(m0 + gid + 8) * 356 + kk + tig];
                a2[2] = Pb[(m0 + gid) * 356 + kk + tig + 4];
                a2[3] = Pb[(m0 + gid + 8) * 356 + kk + tig + 4];
                b2[0] = Vs[(kk + tig) * 40 + wc * 8 + gid];
                b2[1] = Vs[(kk + tig + 4) * 40 + wc * 8 + gid];
                mma_tf32(cva, a2, b2);
            }
            for (int k8 = kmid; k8 < kend; k8++) {
                int kk = k8 * 8;
                unsigned a2[4], b2[2];
                a2[0] = Pb[(m0 + gid) * 356 + kk + tig];
                a2[1] = Pb[(m0 + gid + 8) * 356 + kk + tig];
                a2[2] = Pb[(m0 + gid) * 356 + kk + tig + 4];
                a2[3] = Pb[(m0 + gid + 8) * 356 + kk + tig + 4];
                b2[0] = Vs[(kk + tig) * 40 + wc * 8 + gid];
                b2[1] = Vs[(kk + tig + 4) * 40 + wc * 8 + gid];
                mma_tf32(cvb, a2, b2);
            }
            int cc = wc * 8 + tig * 2;
            float* pp = Pp + (size_t)kh * 64 * 36;
            *(float2*)&pp[(m0 + gid) * 36 + cc] =
                make_float2(cva[0] + cvb[0], cva[1] + cvb[1]);
            *(float2*)&pp[(m0 + gid + 8) * 36 + cc] =
                make_float2(cva[2] + cvb[2], cva[3] + cvb[3]);
        }
        __syncthreads();

        // ---- reduce AV halves + store (512 tasks) ----
        if (tid < 512) {
            int q  = tid >> 3;
            int cg = tid & 7;
            if (q < qn) {
                const float* p0 = Pp + (size_t)q * 36 + cg * 4;
                const float* p1 = p0 + 64 * 36;
                float4 a = *(const float4*)p0;
                float4 b = *(const float4*)p1;
                float inv = Sf[q];
                float4 o = make_float4((a.x + b.x) * inv, (a.y + b.y) * inv,
                                       (a.z + b.z) * inv, (a.w + b.w) * inv);
                *(float4*)(g_ao + ((size_t)(n * LTOK + q0 + q)) * DIMM
                           + h * HEADD + cg * 4) = o;
            }
        }
        __syncthreads();
    }
}

// ======================================================================
extern "C" void kernel_launch(void* const* d_in, const int* in_sizes, int n_in,
                              void* d_out, int out_size)
{
    const float *x = nullptr, *qkvw = nullptr, *tbl = nullptr;
    const float *pw = nullptr, *pb = nullptr;
    const void* mask = nullptr;
    const int* ridx = nullptr;
    for (int i = 0; i < n_in; i++) {
        switch (in_sizes[i]) {
            case 8429568:  x    = (const float*)d_in[i]; break;
            case 442368:   qkvw = (const float*)d_in[i]; break;
            case 26364:    tbl  = (const float*)d_in[i]; break;
            case 147456:   pw   = (const float*)d_in[i]; break;
            case 384:      pb   = (const float*)d_in[i]; break;
            case 7530496:  mask = d_in[i]; break;
            case 117649:   ridx = (const int*)d_in[i]; break;
        }
    }
    if (n_in >= 7) {
        if (!x)    x    = (const float*)d_in[0];
        if (!qkvw) qkvw = (const float*)d_in[1];
        if (!tbl)  tbl  = (const float*)d_in[2];
        if (!pw)   pw   = (const float*)d_in[3];
        if (!pb)   pb   = (const float*)d_in[4];
        if (!mask) mask = d_in[5];
        if (!ridx) ridx = (const int*)d_in[6];
    }

    // 0) mask dtype detection
    detect_mask_kernel<<<1, 256>>>((const unsigned int*)mask);

    // 1) merged prep (maskT + biasT)
    prep_kernel<<<dim3(11, 11, NWIN + 1), dim3(32, 32)>>>(mask, tbl, ridx);

    // 2) QKV projection (tf32 tensor cores) + scatter
    mm_tf32_kernel<<<dim3(172, 18), 256>>>(x, qkvw, MROWS, 3 * DIMM, DIMM, 1,
                                           nullptr, nullptr);

    // 3) tensor-core fused attention, 1024 threads (launch #3 -> ncu)
    size_t smem = 55616u * sizeof(unsigned);   // 222.5 KB
    cudaFuncSetAttribute(attn_kernel,
                         cudaFuncAttributeMaxDynamicSharedMemorySize, (int)smem);
    attn_kernel<<<NWIN * NHEAD, 1024, smem>>>();

    // 4) output projection (tf32 tensor cores) + bias
    mm_tf32_kernel<<<dim3(172, 6), 256>>>(nullptr, pw, MROWS, DIMM, DIMM, 0,
                                          (float*)d_out, pb);
}

// round 13
// speedup vs baseline: 2.6561x; 1.7135x over previous
#include <cuda_runtime.h>

#define NWIN  64
#define NHEAD 12
#define LTOK  343
#define HEADD 32
#define DIMM  384
#define TBLN  2197
#define L2TOK (LTOK*LTOK)
#define LPAD  344
#define QSCALE 0.17677669529663687f
#define LOG2E  1.4426950408889634f
#define QS2   (0.17677669529663687f * 1.4426950408889634f)
#define MROWS (NWIN*LTOK)             // 21952

// -------- scratch (static device globals; no runtime allocation) --------
__device__ __align__(16) float g_q[(size_t)NWIN*NHEAD*LTOK*HEADD];
__device__ __align__(16) float g_k[(size_t)NWIN*NHEAD*LTOK*HEADD];
__device__ __align__(16) float g_v[(size_t)NWIN*NHEAD*LTOK*HEADD];
__device__ __align__(16) float g_ao[(size_t)MROWS*DIMM];
__device__ __align__(16) float g_biasP[(size_t)NHEAD*LTOK*LPAD];        // [h][i][344], *log2e
__device__ __align__(16) unsigned char g_maskP[(size_t)NWIN*LTOK*LPAD]; // [n][i][344]
__device__ int g_mask_mode;   // 0 = 1-byte elements, 1 = 4-byte elements

// ======================================================================
__global__ void detect_mask_kernel(const unsigned int* __restrict__ m)
{
    __shared__ int s_not01, s_notf;
    if (threadIdx.x == 0) { s_not01 = 0; s_notf = 0; }
    __syncthreads();
    int bad01 = 0, badf = 0;
    for (int i = threadIdx.x; i < 4096; i += 256) {
        unsigned int w = m[i];
        if (w > 1u) bad01 = 1;
        if (w != 0u && w != 0x3F800000u) badf = 1;
    }
    if (bad01) atomicOr(&s_not01, 1);
    if (badf)  atomicOr(&s_notf, 1);
    __syncthreads();
    if (threadIdx.x == 0)
        g_mask_mode = (!s_not01 || !s_notf) ? 1 : 0;
}

// ======================================================================
// Prep (padded, NON-transposed):
//  y in [0,NWIN): maskP[y][i][j] = mask[y][i][j]!=0 ; col 343 = 1 (masked)
//  y == NWIN:     biasP[h][i][j] = table[rel_idx[i][j]][h] * log2e ; col 343 = 0
// ======================================================================
__global__ __launch_bounds__(256)
void prep_kernel(const void* __restrict__ mask,
                 const float* __restrict__ table,
                 const int* __restrict__ rel_idx)
{
    const int y = blockIdx.y;
    int e = blockIdx.x * 256 + threadIdx.x;
    if (e >= LTOK * LPAD) return;
    int i = e / LPAD, j = e - i * LPAD;

    if (y < NWIN) {
        unsigned char v = 1;
        if (j < LTOK) {
            size_t src = (size_t)y * L2TOK + (size_t)i * LTOK + j;
            v = g_mask_mode ? (((const unsigned int*)mask)[src] != 0u)
                            : (((const unsigned char*)mask)[src] != 0);
        }
        g_maskP[(size_t)y * LTOK * LPAD + e] = v;
    } else {
        if (j < LTOK) {
            int idx = rel_idx[(size_t)i * LTOK + j];
            const float* trow = table + (size_t)idx * NHEAD;
            #pragma unroll
            for (int h = 0; h < NHEAD; h++)
                g_biasP[(size_t)h * LTOK * LPAD + e] = trow[h] * LOG2E;
        } else {
            #pragma unroll
            for (int h = 0; h < NHEAD; h++)
                g_biasP[(size_t)h * LTOK * LPAD + e] = 0.f;
        }
    }
}

// ======================================================================
// tf32 helpers
// ======================================================================
__device__ __forceinline__ unsigned f2tf32(float f)
{
    unsigned r;
    asm("cvt.rna.tf32.f32 %0, %1;" : "=r"(r) : "f"(f));
    return r;
}

__device__ __forceinline__ float ex2f(float x)
{
    float r;
    asm("ex2.approx.ftz.f32 %0, %1;" : "=f"(r) : "f"(x));
    return r;
}

__device__ __forceinline__ void mma_tf32(float c[4], const unsigned a[4],
                                         const unsigned b[2])
{
    asm volatile(
        "mma.sync.aligned.m16n8k8.row.col.f32.tf32.tf32.f32 "
        "{%0,%1,%2,%3}, {%4,%5,%6,%7}, {%8,%9}, {%0,%1,%2,%3};"
        : "+f"(c[0]), "+f"(c[1]), "+f"(c[2]), "+f"(c[3])
        : "r"(a[0]), "r"(a[1]), "r"(a[2]), "r"(a[3]),
          "r"(b[0]), "r"(b[1]));
}

// ======================================================================
// tf32 tensor-core GEMM (round-7/9 version, unchanged).
// ======================================================================
__global__ __launch_bounds__(256)
void mm_tf32_kernel(const float* __restrict__ Ain, const float* __restrict__ B,
                    int M, int N, int K, int mode,
                    float* __restrict__ C, const float* __restrict__ bias)
{
    __shared__ unsigned As[128][18];
    __shared__ unsigned Bs[16][72];

    const float* A = (mode == 0) ? g_ao : Ain;
    const int tid  = threadIdx.x;
    const int warp = tid >> 5, lane = tid & 31;
    const int wm   = warp & 3;
    const int wn   = warp >> 2;
    const int gid  = lane >> 2, tig = lane & 3;
    const int bm   = blockIdx.x * 128, bn = blockIdx.y * 64;

    float c[2][4][4];
    #pragma unroll
    for (int mt = 0; mt < 2; mt++)
        #pragma unroll
        for (int nt = 0; nt < 4; nt++)
            #pragma unroll
            for (int e = 0; e < 4; e++) c[mt][nt][e] = 0.f;

    for (int k0 = 0; k0 < K; k0 += 16) {
        #pragma unroll
        for (int i = 0; i < 2; i++) {
            int t  = tid + i * 256;
            int m  = t >> 2;
            int c4 = (t & 3) << 2;
            int gr = bm + m;
            float4 v = make_float4(0.f, 0.f, 0.f, 0.f);
            if (gr < M) v = *(const float4*)(A + (size_t)gr * K + k0 + c4);
            As[m][c4 + 0] = f2tf32(v.x);
            As[m][c4 + 1] = f2tf32(v.y);
            As[m][c4 + 2] = f2tf32(v.z);
            As[m][c4 + 3] = f2tf32(v.w);
        }
        {
            int kr = tid >> 4;
            int c4 = (tid & 15) << 2;
            float4 v = *(const float4*)(B + (size_t)(k0 + kr) * N + bn + c4);
            Bs[kr][c4 + 0] = f2tf32(v.x);
            Bs[kr][c4 + 1] = f2tf32(v.y);
            Bs[kr][c4 + 2] = f2tf32(v.z);
            Bs[kr][c4 + 3] = f2tf32(v.w);
        }
        __syncthreads();

        #pragma unroll
        for (int ks = 0; ks < 16; ks += 8) {
            unsigned af[2][4], bf[4][2];
            #pragma unroll
            for (int mt = 0; mt < 2; mt++) {
                int mr = wm * 32 + mt * 16 + gid;
                af[mt][0] = As[mr][ks + tig];
                af[mt][1] = As[mr + 8][ks + tig];
                af[mt][2] = As[mr][ks + tig + 4];
                af[mt][3] = As[mr + 8][ks + tig + 4];
            }
            #pragma unroll
            for (int nt = 0; nt < 4; nt++) {
                int nc = wn * 32 + nt * 8 + gid;
                bf[nt][0] = Bs[ks + tig][nc];
                bf[nt][1] = Bs[ks + tig + 4][nc];
            }
            #pragma unroll
            for (int mt = 0; mt < 2; mt++)
                #pragma unroll
                for (int nt = 0; nt < 4; nt++)
                    mma_tf32(c[mt][nt], af[mt], bf[nt]);
        }
        __syncthreads();
    }

    #pragma unroll
    for (int mt = 0; mt < 2; mt++) {
        int r0 = bm + wm * 32 + mt * 16 + gid;
        int r1 = r0 + 8;
        if (mode == 0) {
            #pragma unroll
            for (int nt = 0; nt < 4; nt++) {
                int col = bn + wn * 32 + nt * 8 + tig * 2;
                float bx = bias[col], by = bias[col + 1];
                if (r0 < M) {
                    float2 o = make_float2(c[mt][nt][0] + bx, c[mt][nt][1] + by);
                    *(float2*)(C + (size_t)r0 * N + col) = o;
                }
                if (r1 < M) {
                    float2 o = make_float2(c[mt][nt][2] + bx, c[mt][nt][3] + by);
                    *(float2*)(C + (size_t)r1 * N + col) = o;
                }
            }
        } else {
            int n0 = r0 / LTOK, l0 = r0 - n0 * LTOK;
            int n1 = r1 / LTOK, l1 = r1 - n1 * LTOK;
            #pragma unroll
            for (int nt = 0; nt < 4; nt++) {
                int colb = bn + wn * 32 + nt * 8 + tig * 2;
                #pragma unroll
                for (int e = 0; e < 4; e++) {
                    int row = (e < 2) ? r0 : r1;
                    if (row >= M) continue;
                    int nn  = (e < 2) ? n0 : n1;
                    int ll  = (e < 2) ? l0 : l1;
                    int col = colb + (e & 1);
                    int s   = col / DIMM;
                    int rem = col - s * DIMM;
                    int hh  = rem >> 5;
                    int cc  = rem & 31;
                    float* dst = (s == 0) ? g_q : ((s == 1) ? g_k : g_v);
                    dst[(((size_t)(nn * NHEAD + hh)) * LTOK + ll) * HEADD + cc]
                        = c[mt][nt][e];
                }
            }
        }
    }
}

// ======================================================================
// Flash attention: 704 threads = 22 warps, warp = one 16-row q-tile.
// Online softmax in registers (log2 domain), zero barriers in main loop.
// smem: Kt[32][360] + Vs[344][40] = 25280 words = 101.1 KB
// ======================================================================
__global__ __launch_bounds__(704, 1)
void attn_kernel()
{
    extern __shared__ unsigned smu[];
    unsigned* Kt = smu;             // [c][j] stride 360
    unsigned* Vs = smu + 11520;     // [j][c] stride 40

    const int tid  = threadIdx.x;
    const int warp = tid >> 5;      // 0..21
    const int lane = tid & 31;
    const int gid  = lane >> 2;     // 0..7
    const int tig  = lane & 3;      // 0..3
    const int bh   = blockIdx.x;
    const int n    = bh / NHEAD;
    const int h    = bh - n * NHEAD;

    // ---- stage K (transposed) + V, tf32 ----
    const float* kg = g_k + (size_t)bh * LTOK * HEADD;
    const float* vg = g_v + (size_t)bh * LTOK * HEADD;
    for (int i = tid; i < LTOK * 8; i += 704) {
        int j = i >> 3, c4 = (i & 7) << 2;
        float4 kv = *(const float4*)(kg + (size_t)i * 4);
        Kt[(c4 + 0) * 360 + j] = f2tf32(kv.x);
        Kt[(c4 + 1) * 360 + j] = f2tf32(kv.y);
        Kt[(c4 + 2) * 360 + j] = f2tf32(kv.z);
        Kt[(c4 + 3) * 360 + j] = f2tf32(kv.w);
        float4 vv = *(const float4*)(vg + (size_t)i * 4);
        uint4 w;
        w.x = f2tf32(vv.x); w.y = f2tf32(vv.y);
        w.z = f2tf32(vv.z); w.w = f2tf32(vv.w);
        *(uint4*)&Vs[j * 40 + c4] = w;
    }
    if (tid < 32) Kt[tid * 360 + 343] = 0;
    if (tid >= 64 && tid < 96) Vs[343 * 40 + (tid - 64)] = 0;
    __syncthreads();    // the only block barrier

    // ---- per-warp rows ----
    const int r0 = warp * 16 + gid;
    const int r1 = r0 + 8;
    const int rc0 = min(r0, LTOK - 1);
    const int rc1 = min(r1, LTOK - 1);

    // Q fragment, pre-scaled by QSCALE*log2e
    const float* qg = g_q + (size_t)bh * LTOK * HEADD;
    unsigned af[4][4];
    #pragma unroll
    for (int ks = 0; ks < 4; ks++) {
        int kk = ks * 8;
        af[ks][0] = f2tf32(qg[rc0 * 32 + kk + tig] * QS2);
        af[ks][1] = f2tf32(qg[rc1 * 32 + kk + tig] * QS2);
        af[ks][2] = f2tf32(qg[rc0 * 32 + kk + tig + 4] * QS2);
        af[ks][3] = f2tf32(qg[rc1 * 32 + kk + tig + 4] * QS2);
    }

    const float* bias0 = g_biasP + ((size_t)h * LTOK + rc0) * LPAD;
    const float* bias1 = g_biasP + ((size_t)h * LTOK + rc1) * LPAD;
    const unsigned char* mk0 = g_maskP + ((size_t)n * LTOK + rc0) * LPAD;
    const unsigned char* mk1 = g_maskP + ((size_t)n * LTOK + rc1) * LPAD;

    float m0 = -1e30f, m1 = -1e30f;
    float l0 = 0.f, l1 = 0.f;
    float O[4][4];
    #pragma unroll
    for (int cg = 0; cg < 4; cg++)
        #pragma unroll
        for (int e = 0; e < 4; e++) O[cg][e] = 0.f;

    const int src_lo = (lane & ~3) | (tig >> 1);
    const int src_hi = src_lo + 2;
    const bool odd = tig & 1;

    for (int jb = 0; jb < 43; jb++) {
        const int n0 = jb * 8;
        const int j0 = n0 + tig * 2;

        // prefetch bias/mask (independent of mma)
        float2 b0 = *(const float2*)(bias0 + j0);
        float2 b1 = *(const float2*)(bias1 + j0);
        unsigned short mm0 = *(const unsigned short*)(mk0 + j0);
        unsigned short mm1 = *(const unsigned short*)(mk1 + j0);

        // score mma (2 independent accumulator pairs)
        float ca[4] = {0.f, 0.f, 0.f, 0.f};
        float cb[4] = {0.f, 0.f, 0.f, 0.f};
        {
            unsigned bf0[2], bf1[2];
            bf0[0] = Kt[(0  + tig) * 360 + n0 + gid];
            bf0[1] = Kt[(4  + tig) * 360 + n0 + gid];
            bf1[0] = Kt[(8  + tig) * 360 + n0 + gid];
            bf1[1] = Kt[(12 + tig) * 360 + n0 + gid];
            mma_tf32(ca, af[0], bf0);
            mma_tf32(cb, af[1], bf1);
            bf0[0] = Kt[(16 + tig) * 360 + n0 + gid];
            bf0[1] = Kt[(20 + tig) * 360 + n0 + gid];
            bf1[0] = Kt[(24 + tig) * 360 + n0 + gid];
            bf1[1] = Kt[(28 + tig) * 360 + n0 + gid];
            mma_tf32(ca, af[2], bf0);
            mma_tf32(cb, af[3], bf1);
        }
        float s0 = (mm0 & 0xff) ? -1e30f : (ca[0] + cb[0] + b0.x);
        float s1 = (mm0 >> 8)   ? -1e30f : (ca[1] + cb[1] + b0.y);
        float s2 = (mm1 & 0xff) ? -1e30f : (ca[2] + cb[2] + b1.x);
        float s3 = (mm1 >> 8)   ? -1e30f : (ca[3] + cb[3] + b1.y);

        // row max of this 8-col block (across 4 tig lanes)
        float mb0 = fmaxf(s0, s1), mb1 = fmaxf(s2, s3);
        mb0 = fmaxf(mb0, __shfl_xor_sync(0xffffffffu, mb0, 1));
        mb0 = fmaxf(mb0, __shfl_xor_sync(0xffffffffu, mb0, 2));
        mb1 = fmaxf(mb1, __shfl_xor_sync(0xffffffffu, mb1, 1));
        mb1 = fmaxf(mb1, __shfl_xor_sync(0xffffffffu, mb1, 2));

        // online rescale only when some row's max moved (warp-uniform)
        bool upd = (mb0 > m0) || (mb1 > m1);
        if (__ballot_sync(0xffffffffu, upd)) {
            float nm0 = fmaxf(m0, mb0), nm1 = fmaxf(m1, mb1);
            float a0 = ex2f(m0 - nm0), a1 = ex2f(m1 - nm1);
            m0 = nm0; m1 = nm1;
            l0 *= a0; l1 *= a1;
            #pragma unroll
            for (int cg = 0; cg < 4; cg++) {
                O[cg][0] *= a0; O[cg][1] *= a0;
                O[cg][2] *= a1; O[cg][3] *= a1;
            }
        }

        float p0 = ex2f(s0 - m0), p1 = ex2f(s1 - m0);
        float p2 = ex2f(s2 - m1), p3 = ex2f(s3 - m1);
        l0 += p0 + p1;
        l1 += p2 + p3;

        // P -> A-fragment layout (intra-quad shuffles)
        unsigned u0 = f2tf32(p0), u1 = f2tf32(p1);
        unsigned u2 = f2tf32(p2), u3 = f2tf32(p3);
        unsigned x0 = __shfl_sync(0xffffffffu, u0, src_lo);
        unsigned x1 = __shfl_sync(0xffffffffu, u1, src_lo);
        unsigned y0 = __shfl_sync(0xffffffffu, u2, src_lo);
        unsigned y1 = __shfl_sync(0xffffffffu, u3, src_lo);
        unsigned z0 = __shfl_sync(0xffffffffu, u0, src_hi);
        unsigned z1 = __shfl_sync(0xffffffffu, u1, src_hi);
        unsigned w0 = __shfl_sync(0xffffffffu, u2, src_hi);
        unsigned w1 = __shfl_sync(0xffffffffu, u3, src_hi);
        unsigned pa[4];
        pa[0] = odd ? x1 : x0;
        pa[1] = odd ? y1 : y0;
        pa[2] = odd ? z1 : z0;
        pa[3] = odd ? w1 : w0;

        // AV: O += P(16x8) @ V(8x32)
        #pragma unroll
        for (int cg = 0; cg < 4; cg++) {
            unsigned bv[2];
            bv[0] = Vs[(n0 + tig) * 40 + cg * 8 + gid];
            bv[1] = Vs[(n0 + tig + 4) * 40 + cg * 8 + gid];
            mma_tf32(O[cg], pa, bv);
        }
    }

    // ---- finalize: reduce l across tig lanes, normalize, store ----
    l0 += __shfl_xor_sync(0xffffffffu, l0, 1);
    l0 += __shfl_xor_sync(0xffffffffu, l0, 2);
    l1 += __shfl_xor_sync(0xffffffffu, l1, 1);
    l1 += __shfl_xor_sync(0xffffffffu, l1, 2);
    float inv0 = 1.f / l0, inv1 = 1.f / l1;

    if (r0 < LTOK) {
        float* og = g_ao + ((size_t)(n * LTOK + r0)) * DIMM + h * HEADD;
        #pragma unroll
        for (int cg = 0; cg < 4; cg++)
            *(float2*)(og + cg * 8 + tig * 2) =
                make_float2(O[cg][0] * inv0, O[cg][1] * inv0);
    }
    if (r1 < LTOK) {
        float* og = g_ao + ((size_t)(n * LTOK + r1)) * DIMM + h * HEADD;
        #pragma unroll
        for (int cg = 0; cg < 4; cg++)
            *(float2*)(og + cg * 8 + tig * 2) =
                make_float2(O[cg][2] * inv1, O[cg][3] * inv1);
    }
}

// ======================================================================
extern "C" void kernel_launch(void* const* d_in, const int* in_sizes, int n_in,
                              void* d_out, int out_size)
{
    const float *x = nullptr, *qkvw = nullptr, *tbl = nullptr;
    const float *pw = nullptr, *pb = nullptr;
    const void* mask = nullptr;
    const int* ridx = nullptr;
    for (int i = 0; i < n_in; i++) {
        switch (in_sizes[i]) {
            case 8429568:  x    = (const float*)d_in[i]; break;
            case 442368:   qkvw = (const float*)d_in[i]; break;
            case 26364:    tbl  = (const float*)d_in[i]; break;
            case 147456:   pw   = (const float*)d_in[i]; break;
            case 384:      pb   = (const float*)d_in[i]; break;
            case 7530496:  mask = d_in[i]; break;
            case 117649:   ridx = (const int*)d_in[i]; break;
        }
    }
    if (n_in >= 7) {
        if (!x)    x    = (const float*)d_in[0];
        if (!qkvw) qkvw = (const float*)d_in[1];
        if (!tbl)  tbl  = (const float*)d_in[2];
        if (!pw)   pw   = (const float*)d_in[3];
        if (!pb)   pb   = (const float*)d_in[4];
        if (!mask) mask = d_in[5];
        if (!ridx) ridx = (const int*)d_in[6];
    }

    // 0) mask dtype detection
    detect_mask_kernel<<<1, 256>>>((const unsigned int*)mask);

    // 1) padded prep (maskP windows + biasP)
    int nb = (LTOK * LPAD + 255) / 256;
    prep_kernel<<<dim3(nb, NWIN + 1), 256>>>(mask, tbl, ridx);

    // 2) QKV projection (tf32 tensor cores) + scatter
    mm_tf32_kernel<<<dim3(172, 18), 256>>>(x, qkvw, MROWS, 3 * DIMM, DIMM, 1,
                                           nullptr, nullptr);

    // 3) flash attention (launch #3 -> ncu capture)
    size_t smem = 25280u * sizeof(unsigned);   // 101.1 KB
    cudaFuncSetAttribute(attn_kernel,
                         cudaFuncAttributeMaxDynamicSharedMemorySize, (int)smem);
    attn_kernel<<<NWIN * NHEAD, 704, smem>>>();

    // 4) output projection (tf32 tensor cores) + bias
    mm_tf32_kernel<<<dim3(172, 6), 256>>>(nullptr, pw, MROWS, DIMM, DIMM, 0,
                                          (float*)d_out, pb);
}

// round 14
// speedup vs baseline: 3.0541x; 1.1498x over previous
#include <cuda_runtime.h>
#include <cuda_fp16.h>

#define NWIN  64
#define NHEAD 12
#define LTOK  343
#define HEADD 32
#define DIMM  384
#define TBLN  2197
#define L2TOK (LTOK*LTOK)
#define LPAD  352
#define QSCALE 0.17677669529663687f
#define LOG2E  1.4426950408889634f
#define QS2   (0.17677669529663687f * 1.4426950408889634f)
#define MROWS (NWIN*LTOK)             // 21952

// -------- scratch (static device globals; no runtime allocation) --------
__device__ __align__(16) float g_q[(size_t)NWIN*NHEAD*LTOK*HEADD];
__device__ __align__(16) float g_k[(size_t)NWIN*NHEAD*LTOK*HEADD];
__device__ __align__(16) float g_v[(size_t)NWIN*NHEAD*LTOK*HEADD];
__device__ __align__(16) float g_ao[(size_t)MROWS*DIMM];
__device__ __align__(16) __half g_biasH[(size_t)NHEAD*LTOK*LPAD];       // *log2e
__device__ __align__(16) unsigned char g_maskP[(size_t)NWIN*LTOK*LPAD]; // pad=1
__device__ int g_mask_mode;   // 0 = 1-byte elements, 1 = 4-byte elements

// ======================================================================
__global__ void detect_mask_kernel(const unsigned int* __restrict__ m)
{
    __shared__ int s_not01, s_notf;
    if (threadIdx.x == 0) { s_not01 = 0; s_notf = 0; }
    __syncthreads();
    int bad01 = 0, badf = 0;
    for (int i = threadIdx.x; i < 4096; i += 256) {
        unsigned int w = m[i];
        if (w > 1u) bad01 = 1;
        if (w != 0u && w != 0x3F800000u) badf = 1;
    }
    if (bad01) atomicOr(&s_not01, 1);
    if (badf)  atomicOr(&s_notf, 1);
    __syncthreads();
    if (threadIdx.x == 0)
        g_mask_mode = (!s_not01 || !s_notf) ? 1 : 0;
}

// ======================================================================
// Prep: y<NWIN: maskP (pad cols -> 1). y==NWIN: biasH = table*log2e (half).
// ======================================================================
__global__ __launch_bounds__(256)
void prep_kernel(const void* __restrict__ mask,
                 const float* __restrict__ table,
                 const int* __restrict__ rel_idx)
{
    const int y = blockIdx.y;
    int e = blockIdx.x * 256 + threadIdx.x;
    if (e >= LTOK * LPAD) return;
    int i = e / LPAD, j = e - i * LPAD;

    if (y < NWIN) {
        unsigned char v = 1;
        if (j < LTOK) {
            size_t src = (size_t)y * L2TOK + (size_t)i * LTOK + j;
            v = g_mask_mode ? (((const unsigned int*)mask)[src] != 0u)
                            : (((const unsigned char*)mask)[src] != 0);
        }
        g_maskP[(size_t)y * LTOK * LPAD + e] = v;
    } else {
        if (j < LTOK) {
            int idx = rel_idx[(size_t)i * LTOK + j];
            const float* trow = table + (size_t)idx * NHEAD;
            #pragma unroll
            for (int h = 0; h < NHEAD; h++)
                g_biasH[(size_t)h * LTOK * LPAD + e] =
                    __float2half(trow[h] * LOG2E);
        } else {
            #pragma unroll
            for (int h = 0; h < NHEAD; h++)
                g_biasH[(size_t)h * LTOK * LPAD + e] = __float2half(0.f);
        }
    }
}

// ======================================================================
// helpers
// ======================================================================
__device__ __forceinline__ unsigned f2tf32(float f)
{
    unsigned r;
    asm("cvt.rna.tf32.f32 %0, %1;" : "=r"(r) : "f"(f));
    return r;
}

__device__ __forceinline__ float ex2f(float x)
{
    float r;
    asm("ex2.approx.ftz.f32 %0, %1;" : "=f"(r) : "f"(x));
    return r;
}

__device__ __forceinline__ unsigned packh2(float a, float b)
{
    __half2 h = __floats2half2_rn(a, b);
    return *(unsigned*)&h;
}

__device__ __forceinline__ void mma_tf32(float c[4], const unsigned a[4],
                                         const unsigned b[2])
{
    asm volatile(
        "mma.sync.aligned.m16n8k8.row.col.f32.tf32.tf32.f32 "
        "{%0,%1,%2,%3}, {%4,%5,%6,%7}, {%8,%9}, {%0,%1,%2,%3};"
        : "+f"(c[0]), "+f"(c[1]), "+f"(c[2]), "+f"(c[3])
        : "r"(a[0]), "r"(a[1]), "r"(a[2]), "r"(a[3]),
          "r"(b[0]), "r"(b[1]));
}

__device__ __forceinline__ void mma_f16(float c[4], const unsigned a[4],
                                        const unsigned b[2])
{
    asm volatile(
        "mma.sync.aligned.m16n8k16.row.col.f32.f16.f16.f32 "
        "{%0,%1,%2,%3}, {%4,%5,%6,%7}, {%8,%9}, {%0,%1,%2,%3};"
        : "+f"(c[0]), "+f"(c[1]), "+f"(c[2]), "+f"(c[3])
        : "r"(a[0]), "r"(a[1]), "r"(a[2]), "r"(a[3]),
          "r"(b[0]), "r"(b[1]));
}

// ======================================================================
// tf32 tensor-core GEMM (unchanged, measured).
// ======================================================================
__global__ __launch_bounds__(256)
void mm_tf32_kernel(const float* __restrict__ Ain, const float* __restrict__ B,
                    int M, int N, int K, int mode,
                    float* __restrict__ C, const float* __restrict__ bias)
{
    __shared__ unsigned As[128][18];
    __shared__ unsigned Bs[16][72];

    const float* A = (mode == 0) ? g_ao : Ain;
    const int tid  = threadIdx.x;
    const int warp = tid >> 5, lane = tid & 31;
    const int wm   = warp & 3;
    const int wn   = warp >> 2;
    const int gid  = lane >> 2, tig = lane & 3;
    const int bm   = blockIdx.x * 128, bn = blockIdx.y * 64;

    float c[2][4][4];
    #pragma unroll
    for (int mt = 0; mt < 2; mt++)
        #pragma unroll
        for (int nt = 0; nt < 4; nt++)
            #pragma unroll
            for (int e = 0; e < 4; e++) c[mt][nt][e] = 0.f;

    for (int k0 = 0; k0 < K; k0 += 16) {
        #pragma unroll
        for (int i = 0; i < 2; i++) {
            int t  = tid + i * 256;
            int m  = t >> 2;
            int c4 = (t & 3) << 2;
            int gr = bm + m;
            float4 v = make_float4(0.f, 0.f, 0.f, 0.f);
            if (gr < M) v = *(const float4*)(A + (size_t)gr * K + k0 + c4);
            As[m][c4 + 0] = f2tf32(v.x);
            As[m][c4 + 1] = f2tf32(v.y);
            As[m][c4 + 2] = f2tf32(v.z);
            As[m][c4 + 3] = f2tf32(v.w);
        }
        {
            int kr = tid >> 4;
            int c4 = (tid & 15) << 2;
            float4 v = *(const float4*)(B + (size_t)(k0 + kr) * N + bn + c4);
            Bs[kr][c4 + 0] = f2tf32(v.x);
            Bs[kr][c4 + 1] = f2tf32(v.y);
            Bs[kr][c4 + 2] = f2tf32(v.z);
            Bs[kr][c4 + 3] = f2tf32(v.w);
        }
        __syncthreads();

        #pragma unroll
        for (int ks = 0; ks < 16; ks += 8) {
            unsigned af[2][4], bf[4][2];
            #pragma unroll
            for (int mt = 0; mt < 2; mt++) {
                int mr = wm * 32 + mt * 16 + gid;
                af[mt][0] = As[mr][ks + tig];
                af[mt][1] = As[mr + 8][ks + tig];
                af[mt][2] = As[mr][ks + tig + 4];
                af[mt][3] = As[mr + 8][ks + tig + 4];
            }
            #pragma unroll
            for (int nt = 0; nt < 4; nt++) {
                int nc = wn * 32 + nt * 8 + gid;
                bf[nt][0] = Bs[ks + tig][nc];
                bf[nt][1] = Bs[ks + tig + 4][nc];
            }
            #pragma unroll
            for (int mt = 0; mt < 2; mt++)
                #pragma unroll
                for (int nt = 0; nt < 4; nt++)
                    mma_tf32(c[mt][nt], af[mt], bf[nt]);
        }
        __syncthreads();
    }

    #pragma unroll
    for (int mt = 0; mt < 2; mt++) {
        int r0 = bm + wm * 32 + mt * 16 + gid;
        int r1 = r0 + 8;
        if (mode == 0) {
            #pragma unroll
            for (int nt = 0; nt < 4; nt++) {
                int col = bn + wn * 32 + nt * 8 + tig * 2;
                float bx = bias[col], by = bias[col + 1];
                if (r0 < M) {
                    float2 o = make_float2(c[mt][nt][0] + bx, c[mt][nt][1] + by);
                    *(float2*)(C + (size_t)r0 * N + col) = o;
                }
                if (r1 < M) {
                    float2 o = make_float2(c[mt][nt][2] + bx, c[mt][nt][3] + by);
                    *(float2*)(C + (size_t)r1 * N + col) = o;
                }
            }
        } else {
            int n0 = r0 / LTOK, l0 = r0 - n0 * LTOK;
            int n1 = r1 / LTOK, l1 = r1 - n1 * LTOK;
            #pragma unroll
            for (int nt = 0; nt < 4; nt++) {
                int colb = bn + wn * 32 + nt * 8 + tig * 2;
                #pragma unroll
                for (int e = 0; e < 4; e++) {
                    int row = (e < 2) ? r0 : r1;
                    if (row >= M) continue;
                    int nn  = (e < 2) ? n0 : n1;
                    int ll  = (e < 2) ? l0 : l1;
                    int col = colb + (e & 1);
                    int s   = col / DIMM;
                    int rem = col - s * DIMM;
                    int hh  = rem >> 5;
                    int cc  = rem & 31;
                    float* dst = (s == 0) ? g_q : ((s == 1) ? g_k : g_v);
                    dst[(((size_t)(nn * NHEAD + hh)) * LTOK + ll) * HEADD + cc]
                        = c[mt][nt][e];
                }
            }
        }
    }
}

// ======================================================================
// fp16 flash attention: 704 threads = 22 warps, warp = one 16-row q-tile.
// m16n8k16: score-C layout == AV-A layout -> zero shuffles.
// smem: Kh2[16][360] + Vh2[32][180] half2 words = 11520 words = 46 KB
// ======================================================================
__global__ __launch_bounds__(704, 1)
void attn_kernel()
{
    extern __shared__ unsigned smu[];
    unsigned* Kh2 = smu;            // [c2][j]  c2=ch/2, stride 360
    unsigned* Vh2 = smu + 5760;     // [c][j2]  j2=j/2, stride 180

    const int tid  = threadIdx.x;
    const int warp = tid >> 5;      // 0..21
    const int lane = tid & 31;
    const int gid  = lane >> 2;     // 0..7
    const int tig  = lane & 3;      // 0..3
    const int bh   = blockIdx.x;
    const int n    = bh / NHEAD;
    const int h    = bh - n * NHEAD;

    // ---- stage K pairs-along-channel, V pairs-along-j ----
    const float* kg = g_k + (size_t)bh * LTOK * HEADD;
    const float* vg = g_v + (size_t)bh * LTOK * HEADD;
    for (int i = tid; i < LTOK * 8; i += 704) {
        int j = i >> 3, c4 = (i & 7) << 2;
        float4 kv = *(const float4*)(kg + (size_t)i * 4);
        Kh2[(c4 >> 1) * 360 + j]       = packh2(kv.x, kv.y);
        Kh2[((c4 >> 1) + 1) * 360 + j] = packh2(kv.z, kv.w);
    }
    if (tid < 256) {    // zero K pad cols 344..359
        int c2 = tid >> 4, j = 344 + (tid & 15);
        Kh2[c2 * 360 + j] = 0;
    }
    for (int i = tid; i < 176 * 8; i += 704) {
        int j2 = i >> 3, c4 = (i & 7) << 2;
        int ja = 2 * j2, jb = ja + 1;
        float4 va = (ja < LTOK)
            ? *(const float4*)(vg + (size_t)ja * 32 + c4)
            : make_float4(0.f, 0.f, 0.f, 0.f);
        float4 vb = (jb < LTOK)
            ? *(const float4*)(vg + (size_t)jb * 32 + c4)
            : make_float4(0.f, 0.f, 0.f, 0.f);
        Vh2[(c4 + 0) * 180 + j2] = packh2(va.x, vb.x);
        Vh2[(c4 + 1) * 180 + j2] = packh2(va.y, vb.y);
        Vh2[(c4 + 2) * 180 + j2] = packh2(va.z, vb.z);
        Vh2[(c4 + 3) * 180 + j2] = packh2(va.w, vb.w);
    }
    __syncthreads();    // only block barrier

    // ---- per-warp rows ----
    const int r0 = warp * 16 + gid;
    const int r1 = r0 + 8;
    const int rc0 = min(r0, LTOK - 1);
    const int rc1 = min(r1, LTOK - 1);

    // Q fragments (pre-scaled), af[kh]: kh=0 -> channels 0-15, kh=1 -> 16-31
    const float* qg = g_q + (size_t)bh * LTOK * HEADD;
    unsigned af[2][4];
    #pragma unroll
    for (int kh = 0; kh < 2; kh++) {
        int cb = kh * 16;
        float2 qa = *(const float2*)(qg + rc0 * 32 + cb + 2 * tig);
        float2 qb = *(const float2*)(qg + rc1 * 32 + cb + 2 * tig);
        float2 qc = *(const float2*)(qg + rc0 * 32 + cb + 8 + 2 * tig);
        float2 qd = *(const float2*)(qg + rc1 * 32 + cb + 8 + 2 * tig);
        af[kh][0] = packh2(qa.x * QS2, qa.y * QS2);
        af[kh][1] = packh2(qb.x * QS2, qb.y * QS2);
        af[kh][2] = packh2(qc.x * QS2, qc.y * QS2);
        af[kh][3] = packh2(qd.x * QS2, qd.y * QS2);
    }

    const __half* bias0 = g_biasH + ((size_t)h * LTOK + rc0) * LPAD;
    const __half* bias1 = g_biasH + ((size_t)h * LTOK + rc1) * LPAD;
    const unsigned char* mk0 = g_maskP + ((size_t)n * LTOK + rc0) * LPAD;
    const unsigned char* mk1 = g_maskP + ((size_t)n * LTOK + rc1) * LPAD;

    float m0 = -1e30f, m1 = -1e30f;
    float l0 = 0.f, l1 = 0.f;
    float O[4][4];
    #pragma unroll
    for (int cg = 0; cg < 4; cg++)
        #pragma unroll
        for (int e = 0; e < 4; e++) O[cg][e] = 0.f;

    for (int jb = 0; jb < 22; jb++) {
        const int n0 = jb * 16;
        const int j0 = n0 + 2 * tig;          // tile0 cols j0,j0+1; tile1 +8

        // prefetch bias (half2) + mask (ushort), both tiles, both rows
        __half2 hb00 = *(const __half2*)(bias0 + j0);
        __half2 hb01 = *(const __half2*)(bias0 + j0 + 8);
        __half2 hb10 = *(const __half2*)(bias1 + j0);
        __half2 hb11 = *(const __half2*)(bias1 + j0 + 8);
        unsigned short mm00 = *(const unsigned short*)(mk0 + j0);
        unsigned short mm01 = *(const unsigned short*)(mk0 + j0 + 8);
        unsigned short mm10 = *(const unsigned short*)(mk1 + j0);
        unsigned short mm11 = *(const unsigned short*)(mk1 + j0 + 8);

        // ---- score mmas: tile0 (cols n0..n0+7), tile1 (n0+8..n0+15) ----
        float ct0[4] = {0.f, 0.f, 0.f, 0.f};
        float ct1[4] = {0.f, 0.f, 0.f, 0.f};
        {
            unsigned b0[2], b1[2];
            b0[0] = Kh2[tig * 360 + n0 + gid];
            b0[1] = Kh2[(4 + tig) * 360 + n0 + gid];
            b1[0] = Kh2[tig * 360 + n0 + 8 + gid];
            b1[1] = Kh2[(4 + tig) * 360 + n0 + 8 + gid];
            mma_f16(ct0, af[0], b0);
            mma_f16(ct1, af[0], b1);
            b0[0] = Kh2[(8 + tig) * 360 + n0 + gid];
            b0[1] = Kh2[(12 + tig) * 360 + n0 + gid];
            b1[0] = Kh2[(8 + tig) * 360 + n0 + 8 + gid];
            b1[1] = Kh2[(12 + tig) * 360 + n0 + 8 + gid];
            mma_f16(ct0, af[1], b0);
            mma_f16(ct1, af[1], b1);
        }
        float2 fb00 = __half22float2(hb00);
        float2 fb01 = __half22float2(hb01);
        float2 fb10 = __half22float2(hb10);
        float2 fb11 = __half22float2(hb11);

        float s00 = (mm00 & 0xff) ? -1e30f : (ct0[0] + fb00.x);
        float s01 = (mm00 >> 8)   ? -1e30f : (ct0[1] + fb00.y);
        float s02 = (mm10 & 0xff) ? -1e30f : (ct0[2] + fb10.x);
        float s03 = (mm10 >> 8)   ? -1e30f : (ct0[3] + fb10.y);
        float s10 = (mm01 & 0xff) ? -1e30f : (ct1[0] + fb01.x);
        float s11 = (mm01 >> 8)   ? -1e30f : (ct1[1] + fb01.y);
        float s12 = (mm11 & 0xff) ? -1e30f : (ct1[2] + fb11.x);
        float s13 = (mm11 >> 8)   ? -1e30f : (ct1[3] + fb11.y);

        // block max per row
        float mb0 = fmaxf(fmaxf(s00, s01), fmaxf(s10, s11));
        float mb1 = fmaxf(fmaxf(s02, s03), fmaxf(s12, s13));
        mb0 = fmaxf(mb0, __shfl_xor_sync(0xffffffffu, mb0, 1));
        mb0 = fmaxf(mb0, __shfl_xor_sync(0xffffffffu, mb0, 2));
        mb1 = fmaxf(mb1, __shfl_xor_sync(0xffffffffu, mb1, 1));
        mb1 = fmaxf(mb1, __shfl_xor_sync(0xffffffffu, mb1, 2));

        bool upd = (mb0 > m0) || (mb1 > m1);
        if (__ballot_sync(0xffffffffu, upd)) {
            float nm0 = fmaxf(m0, mb0), nm1 = fmaxf(m1, mb1);
            float a0 = ex2f(m0 - nm0), a1 = ex2f(m1 - nm1);
            m0 = nm0; m1 = nm1;
            l0 *= a0; l1 *= a1;
            #pragma unroll
            for (int cg = 0; cg < 4; cg++) {
                O[cg][0] *= a0; O[cg][1] *= a0;
                O[cg][2] *= a1; O[cg][3] *= a1;
            }
        }

        float p00 = ex2f(s00 - m0), p01 = ex2f(s01 - m0);
        float p10 = ex2f(s10 - m0), p11 = ex2f(s11 - m0);
        float p02 = ex2f(s02 - m1), p03 = ex2f(s03 - m1);
        float p12 = ex2f(s12 - m1), p13 = ex2f(s13 - m1);
        l0 += (p00 + p01) + (p10 + p11);
        l1 += (p02 + p03) + (p12 + p13);

        // C layout == A layout: pack pairs, no shuffles
        unsigned pa[4];
        pa[0] = packh2(p00, p01);   // tile0, row gid      (k 0-7)
        pa[1] = packh2(p02, p03);   // tile0, row gid+8
        pa[2] = packh2(p10, p11);   // tile1, row gid      (k 8-15)
        pa[3] = packh2(p12, p13);   // tile1, row gid+8

        // ---- AV: O += P(16x16) @ V(16x32) ----
        #pragma unroll
        for (int cg = 0; cg < 4; cg++) {
            unsigned bv[2];
            int c = cg * 8 + gid;
            bv[0] = Vh2[c * 180 + (n0 >> 1) + tig];
            bv[1] = Vh2[c * 180 + (n0 >> 1) + tig + 4];
            mma_f16(O[cg], pa, bv);
        }
    }

    // ---- finalize ----
    l0 += __shfl_xor_sync(0xffffffffu, l0, 1);
    l0 += __shfl_xor_sync(0xffffffffu, l0, 2);
    l1 += __shfl_xor_sync(0xffffffffu, l1, 1);
    l1 += __shfl_xor_sync(0xffffffffu, l1, 2);
    float inv0 = 1.f / l0, inv1 = 1.f / l1;

    if (r0 < LTOK) {
        float* og = g_ao + ((size_t)(n * LTOK + r0)) * DIMM + h * HEADD;
        #pragma unroll
        for (int cg = 0; cg < 4; cg++)
            *(float2*)(og + cg * 8 + tig * 2) =
                make_float2(O[cg][0] * inv0, O[cg][1] * inv0);
    }
    if (r1 < LTOK) {
        float* og = g_ao + ((size_t)(n * LTOK + r1)) * DIMM + h * HEADD;
        #pragma unroll
        for (int cg = 0; cg < 4; cg++)
            *(float2*)(og + cg * 8 + tig * 2) =
                make_float2(O[cg][2] * inv1, O[cg][3] * inv1);
    }
}

// ======================================================================
extern "C" void kernel_launch(void* const* d_in, const int* in_sizes, int n_in,
                              void* d_out, int out_size)
{
    const float *x = nullptr, *qkvw = nullptr, *tbl = nullptr;
    const float *pw = nullptr, *pb = nullptr;
    const void* mask = nullptr;
    const int* ridx = nullptr;
    for (int i = 0; i < n_in; i++) {
        switch (in_sizes[i]) {
            case 8429568:  x    = (const float*)d_in[i]; break;
            case 442368:   qkvw = (const float*)d_in[i]; break;
            case 26364:    tbl  = (const float*)d_in[i]; break;
            case 147456:   pw   = (const float*)d_in[i]; break;
            case 384:      pb   = (const float*)d_in[i]; break;
            case 7530496:  mask = d_in[i]; break;
            case 117649:   ridx = (const int*)d_in[i]; break;
        }
    }
    if (n_in >= 7) {
        if (!x)    x    = (const float*)d_in[0];
        if (!qkvw) qkvw = (const float*)d_in[1];
        if (!tbl)  tbl  = (const float*)d_in[2];
        if (!pw)   pw   = (const float*)d_in[3];
        if (!pb)   pb   = (const float*)d_in[4];
        if (!mask) mask = d_in[5];
        if (!ridx) ridx = (const int*)d_in[6];
    }

    // 0) mask dtype detection
    detect_mask_kernel<<<1, 256>>>((const unsigned int*)mask);

    // 1) padded prep (maskP + biasH)
    int nb = (LTOK * LPAD + 255) / 256;
    prep_kernel<<<dim3(nb, NWIN + 1), 256>>>(mask, tbl, ridx);

    // 2) QKV projection (tf32 tensor cores) + scatter
    mm_tf32_kernel<<<dim3(172, 18), 256>>>(x, qkvw, MROWS, 3 * DIMM, DIMM, 1,
                                           nullptr, nullptr);

    // 3) fp16 flash attention (launch #3 -> ncu capture)
    size_t smem = 11520u * sizeof(unsigned);   // 46 KB
    cudaFuncSetAttribute(attn_kernel,
                         cudaFuncAttributeMaxDynamicSharedMemorySize, (int)smem);
    attn_kernel<<<NWIN * NHEAD, 704, smem>>>();

    // 4) output projection (tf32 tensor cores) + bias
    mm_tf32_kernel<<<dim3(172, 6), 256>>>(nullptr, pw, MROWS, DIMM, DIMM, 0,
                                          (float*)d_out, pb);
}

// round 15
// speedup vs baseline: 3.5343x; 1.1572x over previous
#include <cuda_runtime.h>
#include <cuda_fp16.h>

#define NWIN  64
#define NHEAD 12
#define LTOK  343
#define HEADD 32
#define DIMM  384
#define TBLN  2197
#define L2TOK (LTOK*LTOK)
#define LPAD  352
#define QSCALE 0.17677669529663687f
#define LOG2E  1.4426950408889634f
#define QS2   (0.17677669529663687f * 1.4426950408889634f)
#define MROWS (NWIN*LTOK)             // 21952

// -------- scratch (static device globals; no runtime allocation) --------
__device__ __align__(16) float g_q[(size_t)NWIN*NHEAD*LTOK*HEADD];
__device__ __align__(16) float g_k[(size_t)NWIN*NHEAD*LTOK*HEADD];
__device__ __align__(16) float g_v[(size_t)NWIN*NHEAD*LTOK*HEADD];
__device__ __align__(16) float g_ao[(size_t)MROWS*DIMM];
__device__ __align__(16) __half g_biasH[(size_t)NHEAD*LTOK*LPAD];       // *log2e
__device__ __align__(16) unsigned char g_maskP[(size_t)NWIN*LTOK*LPAD]; // pad=1
__device__ int g_mask_mode;   // 0 = 1-byte elements, 1 = 4-byte elements

// ======================================================================
__global__ void detect_mask_kernel(const unsigned int* __restrict__ m)
{
    __shared__ int s_not01, s_notf;
    if (threadIdx.x == 0) { s_not01 = 0; s_notf = 0; }
    __syncthreads();
    int bad01 = 0, badf = 0;
    for (int i = threadIdx.x; i < 4096; i += 256) {
        unsigned int w = m[i];
        if (w > 1u) bad01 = 1;
        if (w != 0u && w != 0x3F800000u) badf = 1;
    }
    if (bad01) atomicOr(&s_not01, 1);
    if (badf)  atomicOr(&s_notf, 1);
    __syncthreads();
    if (threadIdx.x == 0)
        g_mask_mode = (!s_not01 || !s_notf) ? 1 : 0;
}

// ======================================================================
// Prep: y<NWIN: maskP (pad cols -> 1). y==NWIN: biasH = table*log2e (half).
// ======================================================================
__global__ __launch_bounds__(256)
void prep_kernel(const void* __restrict__ mask,
                 const float* __restrict__ table,
                 const int* __restrict__ rel_idx)
{
    const int y = blockIdx.y;
    int e = blockIdx.x * 256 + threadIdx.x;
    if (e >= LTOK * LPAD) return;
    int i = e / LPAD, j = e - i * LPAD;

    if (y < NWIN) {
        unsigned char v = 1;
        if (j < LTOK) {
            size_t src = (size_t)y * L2TOK + (size_t)i * LTOK + j;
            v = g_mask_mode ? (((const unsigned int*)mask)[src] != 0u)
                            : (((const unsigned char*)mask)[src] != 0);
        }
        g_maskP[(size_t)y * LTOK * LPAD + e] = v;
    } else {
        if (j < LTOK) {
            int idx = rel_idx[(size_t)i * LTOK + j];
            const float* trow = table + (size_t)idx * NHEAD;
            #pragma unroll
            for (int h = 0; h < NHEAD; h++)
                g_biasH[(size_t)h * LTOK * LPAD + e] =
                    __float2half(trow[h] * LOG2E);
        } else {
            #pragma unroll
            for (int h = 0; h < NHEAD; h++)
                g_biasH[(size_t)h * LTOK * LPAD + e] = __float2half(0.f);
        }
    }
}

// ======================================================================
// helpers
// ======================================================================
__device__ __forceinline__ float ex2f(float x)
{
    float r;
    asm("ex2.approx.ftz.f32 %0, %1;" : "=f"(r) : "f"(x));
    return r;
}

__device__ __forceinline__ unsigned packh2(float a, float b)
{
    __half2 h = __floats2half2_rn(a, b);
    return *(unsigned*)&h;
}

__device__ __forceinline__ void mma_f16(float c[4], const unsigned a[4],
                                        const unsigned b[2])
{
    asm volatile(
        "mma.sync.aligned.m16n8k16.row.col.f32.f16.f16.f32 "
        "{%0,%1,%2,%3}, {%4,%5,%6,%7}, {%8,%9}, {%0,%1,%2,%3};"
        : "+f"(c[0]), "+f"(c[1]), "+f"(c[2]), "+f"(c[3])
        : "r"(a[0]), "r"(a[1]), "r"(a[2]), "r"(a[3]),
          "r"(b[0]), "r"(b[1]));
}

// ======================================================================
// fp16 tensor-core GEMM: C(M,N) = A(M,K) @ B(K,N), fp32 accumulate.
// BM=128, BN=64, BK=16; 256 threads = 8 warps (4x2), 32x32 warp tile.
// m16n8k16: 8 MMAs + 16 LDS.32 per BK block (half the tf32 version).
// mode 0: C = g_ao @ B + bias     mode 1: scatter x@qkv_w into g_q/k/v
// ======================================================================
__global__ __launch_bounds__(256)
void mm_f16_kernel(const float* __restrict__ Ain, const float* __restrict__ B,
                   int M, int N, int K, int mode,
                   float* __restrict__ C, const float* __restrict__ bias)
{
    __shared__ unsigned As[128][12];   // [m][k2] half2 words, stride 12
    __shared__ unsigned BsT[64][12];   // [n][k2] half2 words, stride 12

    const float* A = (mode == 0) ? g_ao : Ain;
    const int tid  = threadIdx.x;
    const int warp = tid >> 5, lane = tid & 31;
    const int wm   = warp & 3;
    const int wn   = warp >> 2;
    const int gid  = lane >> 2, tig = lane & 3;
    const int bm   = blockIdx.x * 128, bn = blockIdx.y * 64;

    float c[2][4][4];
    #pragma unroll
    for (int mt = 0; mt < 2; mt++)
        #pragma unroll
        for (int nt = 0; nt < 4; nt++)
            #pragma unroll
            for (int e = 0; e < 4; e++) c[mt][nt][e] = 0.f;

    for (int k0 = 0; k0 < K; k0 += 16) {
        // stage A (128 x 16) -> half2 [m][k2]
        #pragma unroll
        for (int i = 0; i < 2; i++) {
            int t  = tid + i * 256;
            int m  = t >> 2;
            int c4 = (t & 3) << 2;
            int gr = bm + m;
            float4 v = make_float4(0.f, 0.f, 0.f, 0.f);
            if (gr < M) v = *(const float4*)(A + (size_t)gr * K + k0 + c4);
            As[m][(c4 >> 1) + 0] = packh2(v.x, v.y);
            As[m][(c4 >> 1) + 1] = packh2(v.z, v.w);
        }
        // stage B (16 x 64) transposed -> half2 [n][k2]
        // thread: n = tid & 63, kq = tid >> 6 (covers k = 4kq..4kq+3)
        {
            int nn = tid & 63;
            int kq = tid >> 6;
            const float* bp = B + (size_t)(k0 + 4 * kq) * N + bn + nn;
            float b0 = bp[0];
            float b1 = bp[(size_t)N];
            float b2 = bp[(size_t)2 * N];
            float b3 = bp[(size_t)3 * N];
            BsT[nn][kq * 2 + 0] = packh2(b0, b1);
            BsT[nn][kq * 2 + 1] = packh2(b2, b3);
        }
        __syncthreads();

        unsigned af[2][4], bf[4][2];
        #pragma unroll
        for (int mt = 0; mt < 2; mt++) {
            int mr = wm * 32 + mt * 16 + gid;
            af[mt][0] = As[mr][tig];
            af[mt][1] = As[mr + 8][tig];
            af[mt][2] = As[mr][tig + 4];
            af[mt][3] = As[mr + 8][tig + 4];
        }
        #pragma unroll
        for (int nt = 0; nt < 4; nt++) {
            int nc = wn * 32 + nt * 8 + gid;
            bf[nt][0] = BsT[nc][tig];
            bf[nt][1] = BsT[nc][tig + 4];
        }
        #pragma unroll
        for (int mt = 0; mt < 2; mt++)
            #pragma unroll
            for (int nt = 0; nt < 4; nt++)
                mma_f16(c[mt][nt], af[mt], bf[nt]);
        __syncthreads();
    }

    // ---- epilogue (same C layout as k8 version) ----
    #pragma unroll
    for (int mt = 0; mt < 2; mt++) {
        int r0 = bm + wm * 32 + mt * 16 + gid;
        int r1 = r0 + 8;
        if (mode == 0) {
            #pragma unroll
            for (int nt = 0; nt < 4; nt++) {
                int col = bn + wn * 32 + nt * 8 + tig * 2;
                float bx = bias[col], by = bias[col + 1];
                if (r0 < M) {
                    float2 o = make_float2(c[mt][nt][0] + bx, c[mt][nt][1] + by);
                    *(float2*)(C + (size_t)r0 * N + col) = o;
                }
                if (r1 < M) {
                    float2 o = make_float2(c[mt][nt][2] + bx, c[mt][nt][3] + by);
                    *(float2*)(C + (size_t)r1 * N + col) = o;
                }
            }
        } else {
            int n0 = r0 / LTOK, l0 = r0 - n0 * LTOK;
            int n1 = r1 / LTOK, l1 = r1 - n1 * LTOK;
            #pragma unroll
            for (int nt = 0; nt < 4; nt++) {
                int colb = bn + wn * 32 + nt * 8 + tig * 2;
                #pragma unroll
                for (int e = 0; e < 4; e++) {
                    int row = (e < 2) ? r0 : r1;
                    if (row >= M) continue;
                    int nn  = (e < 2) ? n0 : n1;
                    int ll  = (e < 2) ? l0 : l1;
                    int col = colb + (e & 1);
                    int s   = col / DIMM;
                    int rem = col - s * DIMM;
                    int hh  = rem >> 5;
                    int cc  = rem & 31;
                    float* dst = (s == 0) ? g_q : ((s == 1) ? g_k : g_v);
                    dst[(((size_t)(nn * NHEAD + hh)) * LTOK + ll) * HEADD + cc]
                        = c[mt][nt][e];
                }
            }
        }
    }
}

// ======================================================================
// fp16 flash attention (round-14, measured 128us): 704 thr = 22 warps.
// ======================================================================
__global__ __launch_bounds__(704, 1)
void attn_kernel()
{
    extern __shared__ unsigned smu[];
    unsigned* Kh2 = smu;            // [c2][j]  stride 360
    unsigned* Vh2 = smu + 5760;     // [c][j2]  stride 180

    const int tid  = threadIdx.x;
    const int warp = tid >> 5;
    const int lane = tid & 31;
    const int gid  = lane >> 2;
    const int tig  = lane & 3;
    const int bh   = blockIdx.x;
    const int n    = bh / NHEAD;
    const int h    = bh - n * NHEAD;

    const float* kg = g_k + (size_t)bh * LTOK * HEADD;
    const float* vg = g_v + (size_t)bh * LTOK * HEADD;
    for (int i = tid; i < LTOK * 8; i += 704) {
        int j = i >> 3, c4 = (i & 7) << 2;
        float4 kv = *(const float4*)(kg + (size_t)i * 4);
        Kh2[(c4 >> 1) * 360 + j]       = packh2(kv.x, kv.y);
        Kh2[((c4 >> 1) + 1) * 360 + j] = packh2(kv.z, kv.w);
    }
    if (tid < 256) {
        int c2 = tid >> 4, j = 344 + (tid & 15);
        Kh2[c2 * 360 + j] = 0;
    }
    for (int i = tid; i < 176 * 8; i += 704) {
        int j2 = i >> 3, c4 = (i & 7) << 2;
        int ja = 2 * j2, jb = ja + 1;
        float4 va = (ja < LTOK)
            ? *(const float4*)(vg + (size_t)ja * 32 + c4)
            : make_float4(0.f, 0.f, 0.f, 0.f);
        float4 vb = (jb < LTOK)
            ? *(const float4*)(vg + (size_t)jb * 32 + c4)
            : make_float4(0.f, 0.f, 0.f, 0.f);
        Vh2[(c4 + 0) * 180 + j2] = packh2(va.x, vb.x);
        Vh2[(c4 + 1) * 180 + j2] = packh2(va.y, vb.y);
        Vh2[(c4 + 2) * 180 + j2] = packh2(va.z, vb.z);
        Vh2[(c4 + 3) * 180 + j2] = packh2(va.w, vb.w);
    }
    __syncthreads();

    const int r0 = warp * 16 + gid;
    const int r1 = r0 + 8;
    const int rc0 = min(r0, LTOK - 1);
    const int rc1 = min(r1, LTOK - 1);

    const float* qg = g_q + (size_t)bh * LTOK * HEADD;
    unsigned af[2][4];
    #pragma unroll
    for (int kh = 0; kh < 2; kh++) {
        int cb = kh * 16;
        float2 qa = *(const float2*)(qg + rc0 * 32 + cb + 2 * tig);
        float2 qb = *(const float2*)(qg + rc1 * 32 + cb + 2 * tig);
        float2 qc = *(const float2*)(qg + rc0 * 32 + cb + 8 + 2 * tig);
        float2 qd = *(const float2*)(qg + rc1 * 32 + cb + 8 + 2 * tig);
        af[kh][0] = packh2(qa.x * QS2, qa.y * QS2);
        af[kh][1] = packh2(qb.x * QS2, qb.y * QS2);
        af[kh][2] = packh2(qc.x * QS2, qc.y * QS2);
        af[kh][3] = packh2(qd.x * QS2, qd.y * QS2);
    }

    const __half* bias0 = g_biasH + ((size_t)h * LTOK + rc0) * LPAD;
    const __half* bias1 = g_biasH + ((size_t)h * LTOK + rc1) * LPAD;
    const unsigned char* mk0 = g_maskP + ((size_t)n * LTOK + rc0) * LPAD;
    const unsigned char* mk1 = g_maskP + ((size_t)n * LTOK + rc1) * LPAD;

    float m0 = -1e30f, m1 = -1e30f;
    float l0 = 0.f, l1 = 0.f;
    float O[4][4];
    #pragma unroll
    for (int cg = 0; cg < 4; cg++)
        #pragma unroll
        for (int e = 0; e < 4; e++) O[cg][e] = 0.f;

    for (int jb = 0; jb < 22; jb++) {
        const int n0 = jb * 16;
        const int j0 = n0 + 2 * tig;

        __half2 hb00 = *(const __half2*)(bias0 + j0);
        __half2 hb01 = *(const __half2*)(bias0 + j0 + 8);
        __half2 hb10 = *(const __half2*)(bias1 + j0);
        __half2 hb11 = *(const __half2*)(bias1 + j0 + 8);
        unsigned short mm00 = *(const unsigned short*)(mk0 + j0);
        unsigned short mm01 = *(const unsigned short*)(mk0 + j0 + 8);
        unsigned short mm10 = *(const unsigned short*)(mk1 + j0);
        unsigned short mm11 = *(const unsigned short*)(mk1 + j0 + 8);

        float ct0[4] = {0.f, 0.f, 0.f, 0.f};
        float ct1[4] = {0.f, 0.f, 0.f, 0.f};
        {
            unsigned b0[2], b1[2];
            b0[0] = Kh2[tig * 360 + n0 + gid];
            b0[1] = Kh2[(4 + tig) * 360 + n0 + gid];
            b1[0] = Kh2[tig * 360 + n0 + 8 + gid];
            b1[1] = Kh2[(4 + tig) * 360 + n0 + 8 + gid];
            mma_f16(ct0, af[0], b0);
            mma_f16(ct1, af[0], b1);
            b0[0] = Kh2[(8 + tig) * 360 + n0 + gid];
            b0[1] = Kh2[(12 + tig) * 360 + n0 + gid];
            b1[0] = Kh2[(8 + tig) * 360 + n0 + 8 + gid];
            b1[1] = Kh2[(12 + tig) * 360 + n0 + 8 + gid];
            mma_f16(ct0, af[1], b0);
            mma_f16(ct1, af[1], b1);
        }
        float2 fb00 = __half22float2(hb00);
        float2 fb01 = __half22float2(hb01);
        float2 fb10 = __half22float2(hb10);
        float2 fb11 = __half22float2(hb11);

        float s00 = (mm00 & 0xff) ? -1e30f : (ct0[0] + fb00.x);
        float s01 = (mm00 >> 8)   ? -1e30f : (ct0[1] + fb00.y);
        float s02 = (mm10 & 0xff) ? -1e30f : (ct0[2] + fb10.x);
        float s03 = (mm10 >> 8)   ? -1e30f : (ct0[3] + fb10.y);
        float s10 = (mm01 & 0xff) ? -1e30f : (ct1[0] + fb01.x);
        float s11 = (mm01 >> 8)   ? -1e30f : (ct1[1] + fb01.y);
        float s12 = (mm11 & 0xff) ? -1e30f : (ct1[2] + fb11.x);
        float s13 = (mm11 >> 8)   ? -1e30f : (ct1[3] + fb11.y);

        float mb0 = fmaxf(fmaxf(s00, s01), fmaxf(s10, s11));
        float mb1 = fmaxf(fmaxf(s02, s03), fmaxf(s12, s13));
        mb0 = fmaxf(mb0, __shfl_xor_sync(0xffffffffu, mb0, 1));
        mb0 = fmaxf(mb0, __shfl_xor_sync(0xffffffffu, mb0, 2));
        mb1 = fmaxf(mb1, __shfl_xor_sync(0xffffffffu, mb1, 1));
        mb1 = fmaxf(mb1, __shfl_xor_sync(0xffffffffu, mb1, 2));

        bool upd = (mb0 > m0) || (mb1 > m1);
        if (__ballot_sync(0xffffffffu, upd)) {
            float nm0 = fmaxf(m0, mb0), nm1 = fmaxf(m1, mb1);
            float a0 = ex2f(m0 - nm0), a1 = ex2f(m1 - nm1);
            m0 = nm0; m1 = nm1;
            l0 *= a0; l1 *= a1;
            #pragma unroll
            for (int cg = 0; cg < 4; cg++) {
                O[cg][0] *= a0; O[cg][1] *= a0;
                O[cg][2] *= a1; O[cg][3] *= a1;
            }
        }

        float p00 = ex2f(s00 - m0), p01 = ex2f(s01 - m0);
        float p10 = ex2f(s10 - m0), p11 = ex2f(s11 - m0);
        float p02 = ex2f(s02 - m1), p03 = ex2f(s03 - m1);
        float p12 = ex2f(s12 - m1), p13 = ex2f(s13 - m1);
        l0 += (p00 + p01) + (p10 + p11);
        l1 += (p02 + p03) + (p12 + p13);

        unsigned pa[4];
        pa[0] = packh2(p00, p01);
        pa[1] = packh2(p02, p03);
        pa[2] = packh2(p10, p11);
        pa[3] = packh2(p12, p13);

        #pragma unroll
        for (int cg = 0; cg < 4; cg++) {
            unsigned bv[2];
            int c = cg * 8 + gid;
            bv[0] = Vh2[c * 180 + (n0 >> 1) + tig];
            bv[1] = Vh2[c * 180 + (n0 >> 1) + tig + 4];
            mma_f16(O[cg], pa, bv);
        }
    }

    l0 += __shfl_xor_sync(0xffffffffu, l0, 1);
    l0 += __shfl_xor_sync(0xffffffffu, l0, 2);
    l1 += __shfl_xor_sync(0xffffffffu, l1, 1);
    l1 += __shfl_xor_sync(0xffffffffu, l1, 2);
    float inv0 = 1.f / l0, inv1 = 1.f / l1;

    if (r0 < LTOK) {
        float* og = g_ao + ((size_t)(n * LTOK + r0)) * DIMM + h * HEADD;
        #pragma unroll
        for (int cg = 0; cg < 4; cg++)
            *(float2*)(og + cg * 8 + tig * 2) =
                make_float2(O[cg][0] * inv0, O[cg][1] * inv0);
    }
    if (r1 < LTOK) {
        float* og = g_ao + ((size_t)(n * LTOK + r1)) * DIMM + h * HEADD;
        #pragma unroll
        for (int cg = 0; cg < 4; cg++)
            *(float2*)(og + cg * 8 + tig * 2) =
                make_float2(O[cg][2] * inv1, O[cg][3] * inv1);
    }
}

// ======================================================================
extern "C" void kernel_launch(void* const* d_in, const int* in_sizes, int n_in,
                              void* d_out, int out_size)
{
    const float *x = nullptr, *qkvw = nullptr, *tbl = nullptr;
    const float *pw = nullptr, *pb = nullptr;
    const void* mask = nullptr;
    const int* ridx = nullptr;
    for (int i = 0; i < n_in; i++) {
        switch (in_sizes[i]) {
            case 8429568:  x    = (const float*)d_in[i]; break;
            case 442368:   qkvw = (const float*)d_in[i]; break;
            case 26364:    tbl  = (const float*)d_in[i]; break;
            case 147456:   pw   = (const float*)d_in[i]; break;
            case 384:      pb   = (const float*)d_in[i]; break;
            case 7530496:  mask = d_in[i]; break;
            case 117649:   ridx = (const int*)d_in[i]; break;
        }
    }
    if (n_in >= 7) {
        if (!x)    x    = (const float*)d_in[0];
        if (!qkvw) qkvw = (const float*)d_in[1];
        if (!tbl)  tbl  = (const float*)d_in[2];
        if (!pw)   pw   = (const float*)d_in[3];
        if (!pb)   pb   = (const float*)d_in[4];
        if (!mask) mask = d_in[5];
        if (!ridx) ridx = (const int*)d_in[6];
    }

    // 0) mask dtype detection
    detect_mask_kernel<<<1, 256>>>((const unsigned int*)mask);

    // 1) padded prep (maskP + biasH)
    int nb = (LTOK * LPAD + 255) / 256;
    prep_kernel<<<dim3(nb, NWIN + 1), 256>>>(mask, tbl, ridx);

    // 2) QKV projection (fp16 tensor cores) + scatter
    mm_f16_kernel<<<dim3(172, 18), 256>>>(x, qkvw, MROWS, 3 * DIMM, DIMM, 1,
                                          nullptr, nullptr);

    // 3) fp16 flash attention (launch #3 -> ncu capture)
    size_t smem = 11520u * sizeof(unsigned);   // 46 KB
    cudaFuncSetAttribute(attn_kernel,
                         cudaFuncAttributeMaxDynamicSharedMemorySize, (int)smem);
    attn_kernel<<<NWIN * NHEAD, 704, smem>>>();

    // 4) output projection (fp16 tensor cores) + bias
    mm_f16_kernel<<<dim3(172, 6), 256>>>(nullptr, pw, MROWS, DIMM, DIMM, 0,
                                         (float*)d_out, pb);
}